// round 13
// baseline (speedup 1.0000x reference)
#include <cuda_runtime.h>
#include <cuda_fp16.h>
#include <math.h>
#include <stdint.h>

#define Bb 4
#define Ss 2048
#define Dd 512
#define Hh 8
#define DK 64
#define BS (Bb*Ss)          // 8192 rows
#define LN_EPS 1e-5f
#define NEG_BIG (-1e30f)

// ---------------- scratch (static device globals; no allocation) ----------------
__device__ float g_xn[3][(size_t)BS*Dd];                 // normalized q,k,v (tf32-rounded)
__device__ float g_qkvh[2][(size_t)Bb*Hh*Ss*DK];         // head-major Q,K (tf32-rounded)
__device__ float g_vt[(size_t)Bb*Hh*DK*Ss];              // V transposed per (b,h): [d][key]
__device__ float g_x[(size_t)BS*Dd];                     // attention output (tf32-rounded)
__device__ float g_wt[4][(size_t)Dd*Dd];                 // W^T, tf32-rounded: [n][k]
__device__ float g_bias2[(size_t)Ss*Ss];                 // bias in mma-fragment order (16.8 MB)
__device__ uint2 g_e[(size_t)Bb*Hh*(Ss/128)*(Ss/128)*16*256]; // fp16 e, fragment order (268 MB)

// ---------------- helpers ----------------
__device__ __forceinline__ uint32_t f2tf32(float x) {
    uint32_t r;
    asm volatile("cvt.rna.tf32.f32 %0, %1;" : "=r"(r) : "f"(x));
    return r;
}
__device__ __forceinline__ float rnd_tf32(float x) { return __uint_as_float(f2tf32(x)); }

__device__ __forceinline__ void mma_tf32(float4& d, const uint32_t a[4],
                                         uint32_t b0, uint32_t b1) {
    asm volatile(
        "mma.sync.aligned.m16n8k8.row.col.f32.tf32.tf32.f32 "
        "{%0,%1,%2,%3}, {%4,%5,%6,%7}, {%8,%9}, {%0,%1,%2,%3};\n"
        : "+f"(d.x), "+f"(d.y), "+f"(d.z), "+f"(d.w)
        : "r"(a[0]), "r"(a[1]), "r"(a[2]), "r"(a[3]), "r"(b0), "r"(b1));
}

__device__ __forceinline__ void cpa16(float* s, const float* g) {
    uint32_t sa = (uint32_t)__cvta_generic_to_shared(s);
    asm volatile("cp.async.ca.shared.global [%0], [%1], 16;\n" :: "r"(sa), "l"(g));
}
#define CP_COMMIT() asm volatile("cp.async.commit_group;\n")
template<int N> __device__ __forceinline__ void cp_wait() {
    asm volatile("cp.async.wait_group %0;\n" :: "n"(N));
}

// ---------------- Kernel 0: pack mask+pos into mma-fragment-ordered bias ----------------
__global__ void __launch_bounds__(1024) bias2_kernel(
    const float* __restrict__ pos, const int* __restrict__ mask) {
    int idx = blockIdx.x * 1024 + threadIdx.x;      // 0 .. 1,048,575
    int lane = idx & 31;
    int j    = (idx >> 5) & 7;
    int w    = (idx >> 8) & 15;
    int kt   = (idx >> 12) & 15;
    int qt   = idx >> 16;                            // 0..15
    int g = lane >> 2, t = lane & 3;
    int wq = w >> 1, wk2 = w & 1;
    int q = qt * 128 + wq * 16 + g;
    int c = kt * 128 + wk2 * 64 + j * 8 + 2 * t;
    const float* p0 = &pos[q * Ss + c];
    const float* p1 = &pos[(q + 8) * Ss + c];
    const int*   m0 = &mask[q * Ss + c];
    const int*   m1 = &mask[(q + 8) * Ss + c];
    float4 o;
    o.x = m0[0] ? p0[0] : NEG_BIG;
    o.y = m0[1] ? p0[1] : NEG_BIG;
    o.z = m1[0] ? p1[0] : NEG_BIG;
    o.w = m1[1] ? p1[1] : NEG_BIG;
    ((float4*)g_bias2)[idx] = o;
}

// ---------------- Kernel 1: LayerNorm (tf32-rounded output) ----------------
__global__ void ln_kernel(const float* __restrict__ q, const float* __restrict__ k,
                          const float* __restrict__ v, const float* __restrict__ g,
                          const float* __restrict__ b) {
    int row = blockIdx.x;
    int which = blockIdx.y;
    const float* xs = which == 0 ? q : (which == 1 ? k : v);
    const float* x = xs + (size_t)row * Dd;
    float* y = g_xn[which] + (size_t)row * Dd;
    int t = threadIdx.x;

    float v0 = x[t], v1 = x[t + 256];
    float s = v0 + v1, s2 = v0 * v0 + v1 * v1;

    __shared__ float rs[8], rs2[8];
    #pragma unroll
    for (int o = 16; o; o >>= 1) {
        s  += __shfl_xor_sync(0xFFFFFFFFu, s,  o);
        s2 += __shfl_xor_sync(0xFFFFFFFFu, s2, o);
    }
    if ((t & 31) == 0) { rs[t >> 5] = s; rs2[t >> 5] = s2; }
    __syncthreads();
    __shared__ float smu, sinv;
    if (t == 0) {
        float S = 0.f, S2 = 0.f;
        #pragma unroll
        for (int i = 0; i < 8; i++) { S += rs[i]; S2 += rs2[i]; }
        float mu = S * (1.f / 512.f);
        float var = S2 * (1.f / 512.f) - mu * mu;
        smu = mu; sinv = rsqrtf(var + LN_EPS);
    }
    __syncthreads();
    float mu = smu, inv = sinv;
    y[t]       = rnd_tf32((v0 - mu) * inv * g[t]       + b[t]);
    y[t + 256] = rnd_tf32((v1 - mu) * inv * g[t + 256] + b[t + 256]);
}

// ---------------- Kernel 1b: weight transpose + tf32 round ----------------
__global__ void wt_kernel(const float* __restrict__ wq, const float* __restrict__ wk,
                          const float* __restrict__ wv, const float* __restrict__ wo) {
    __shared__ float tile[32][33];
    int z = blockIdx.z;
    const float* W = z == 0 ? wq : (z == 1 ? wk : (z == 2 ? wv : wo));
    int k0 = blockIdx.x * 32, n0 = blockIdx.y * 32;
    int c = threadIdx.x & 31, r0 = threadIdx.x >> 5;
    #pragma unroll
    for (int i = 0; i < 4; i++) {
        int r = r0 + i * 8;
        tile[r][c] = W[(size_t)(k0 + r) * Dd + n0 + c];
    }
    __syncthreads();
    #pragma unroll
    for (int i = 0; i < 4; i++) {
        int r = r0 + i * 8;
        g_wt[z][(size_t)(n0 + r) * Dd + k0 + c] = rnd_tf32(tile[c][r]);
    }
}

// ---------------- tf32 GEMM tile core (BM=64, BN=64, BK=32, cp.async 2-stage) ----------------
#define GSTG 2560   // one stage: 64 rows * 40

__device__ __forceinline__ void gemm_load_stage(
    const float* __restrict__ A, const float* __restrict__ Bt,
    int m0, int n0, int k0, float* sA, float* sB) {
    int tid = threadIdx.x;
    #pragma unroll
    for (int i = 0; i < 2; i++) {
        int idx = tid + i * 256;
        int m = idx >> 3, c = idx & 7;
        cpa16(&sA[m * 40 + c * 4], &A[(size_t)(m0 + m) * Dd + k0 + c * 4]);
    }
    #pragma unroll
    for (int i = 0; i < 2; i++) {
        int idx = tid + i * 256;
        int n = idx >> 3, c = idx & 7;
        cpa16(&sB[n * 40 + c * 4], &Bt[(size_t)(n0 + n) * Dd + k0 + c * 4]);
    }
}

__device__ __forceinline__ void gemm_tile_tf32(
    const float* __restrict__ A, const float* __restrict__ Bt,
    int m0, int n0, float4 acc[2][2], float* sA, float* sB) {
    int tid = threadIdx.x;
    int lane = tid & 31, w = tid >> 5;
    int g = lane >> 2, t = lane & 3;
    int wm = w >> 2, wn = w & 3;
    #pragma unroll
    for (int i = 0; i < 2; i++)
        #pragma unroll
        for (int j = 0; j < 2; j++) acc[i][j] = make_float4(0.f, 0.f, 0.f, 0.f);

    gemm_load_stage(A, Bt, m0, n0, 0, sA, sB);
    CP_COMMIT();

    for (int it = 0; it < 16; it++) {
        if (it < 15) {
            int s = (it + 1) & 1;
            gemm_load_stage(A, Bt, m0, n0, (it + 1) * 32, sA + s * GSTG, sB + s * GSTG);
            CP_COMMIT();
            cp_wait<1>();
        } else {
            cp_wait<0>();
        }
        __syncthreads();

        const float* cA = sA + (it & 1) * GSTG;
        const float* cB = sB + (it & 1) * GSTG;
        #pragma unroll
        for (int ks = 0; ks < 4; ks++) {
            int kk = ks * 8;
            uint32_t a[2][4];
            #pragma unroll
            for (int mi = 0; mi < 2; mi++) {
                const float* ap  = &cA[(wm * 32 + mi * 16 + g) * 40 + kk + 2 * t];
                const float* ap2 = ap + 8 * 40;
                float2 lo = *(const float2*)ap;
                float2 hi = *(const float2*)ap2;
                a[mi][0] = __float_as_uint(lo.x);
                a[mi][1] = __float_as_uint(hi.x);
                a[mi][2] = __float_as_uint(lo.y);
                a[mi][3] = __float_as_uint(hi.y);
            }
            #pragma unroll
            for (int nj = 0; nj < 2; nj++) {
                const float* bp = &cB[(wn * 16 + nj * 8 + g) * 40 + kk + 2 * t];
                float2 bb = *(const float2*)bp;
                uint32_t b0 = __float_as_uint(bb.x);
                uint32_t b1 = __float_as_uint(bb.y);
                mma_tf32(acc[0][nj], a[0], b0, b1);
                mma_tf32(acc[1][nj], a[1], b0, b1);
            }
        }
        __syncthreads();
    }
}

// ---------------- Kernel 2: QKV projection (Q,K head-major; V transposed) ----------------
__global__ void __launch_bounds__(256) proj_qkv_kernel(
    const float* __restrict__ bq, const float* __restrict__ bk, const float* __restrict__ bv) {
    __shared__ float sA[2 * GSTG];
    __shared__ float sB[2 * GSTG];
    int z = blockIdx.z;
    const float* bias = z == 0 ? bq : (z == 1 ? bk : bv);
    int m0 = blockIdx.x * 64, n0 = blockIdx.y * 64;

    float4 acc[2][2];
    gemm_tile_tf32(g_xn[z], g_wt[z], m0, n0, acc, sA, sB);

    int lane = threadIdx.x & 31, w = threadIdx.x >> 5;
    int g = lane >> 2, t = lane & 3;
    int wm = w >> 2, wn = w & 3;
    #pragma unroll
    for (int mi = 0; mi < 2; mi++) {
        #pragma unroll
        for (int nj = 0; nj < 2; nj++) {
            int n = n0 + wn * 16 + nj * 8 + 2 * t;
            int hh = n >> 6, dd = n & 63;
            float b0 = bias[n], b1 = bias[n + 1];
            #pragma unroll
            for (int r = 0; r < 2; r++) {
                int m = m0 + wm * 32 + mi * 16 + g + r * 8;
                int bidx = m >> 11, srow = m & 2047;
                float2 val;
                if (r == 0) { val.x = acc[mi][nj].x + b0; val.y = acc[mi][nj].y + b1; }
                else        { val.x = acc[mi][nj].z + b0; val.y = acc[mi][nj].w + b1; }
                val.x = rnd_tf32(val.x); val.y = rnd_tf32(val.y);
                if (z == 2) {
                    // V transposed: VT[(bh)*64 + d][key]
                    float* VT = g_vt + (size_t)(bidx * Hh + hh) * DK * Ss;
                    VT[(size_t)dd * Ss + srow]       = val.x;
                    VT[(size_t)(dd + 1) * Ss + srow] = val.y;
                } else {
                    float* out = g_qkvh[z];
                    *(float2*)&out[(((size_t)(bidx * Hh + hh) * Ss + srow) * DK) + dd] = val;
                }
            }
        }
    }
}

// ---------------- Kernel 4: output projection ----------------
__global__ void __launch_bounds__(256) proj_out_kernel(
    const float* __restrict__ bo, const float* __restrict__ ls, float* __restrict__ Cout) {
    __shared__ float sA[2 * GSTG];
    __shared__ float sB[2 * GSTG];
    int m0 = blockIdx.x * 64, n0 = blockIdx.y * 64;

    float4 acc[2][2];
    gemm_tile_tf32(g_x, g_wt[3], m0, n0, acc, sA, sB);

    int lane = threadIdx.x & 31, w = threadIdx.x >> 5;
    int g = lane >> 2, t = lane & 3;
    int wm = w >> 2, wn = w & 3;
    #pragma unroll
    for (int mi = 0; mi < 2; mi++) {
        #pragma unroll
        for (int nj = 0; nj < 2; nj++) {
            int n = n0 + wn * 16 + nj * 8 + 2 * t;
            float b0 = bo[n], b1 = bo[n + 1];
            float l0 = ls[n], l1 = ls[n + 1];
            #pragma unroll
            for (int r = 0; r < 2; r++) {
                int m = m0 + wm * 32 + mi * 16 + g + r * 8;
                float2 val;
                if (r == 0) { val.x = (acc[mi][nj].x + b0) * l0; val.y = (acc[mi][nj].y + b1) * l1; }
                else        { val.x = (acc[mi][nj].z + b0) * l0; val.y = (acc[mi][nj].w + b1) * l1; }
                *(float2*)&Cout[(size_t)m * Dd + n] = val;
            }
        }
    }
}

// ---------------- Kernel 3: attention — TQ=128, fp16-e scratch, VT for PV ----------------
#define KSTRIDE 72
#define VTSTRIDE 136
#define SK_ELEMS (128 * KSTRIDE)      // 9216
#define SVT_ELEMS (64 * VTSTRIDE)     // 8704
#define ATTN_SMEM_BYTES (2 * SK_ELEMS * 4)   // 73,728 (VT buffers alias; smaller)
#define FULLM 0xFFFFFFFFu

__device__ __forceinline__ void stage_k(const float* __restrict__ K, int kt, float* dst) {
    int tid = threadIdx.x;
    #pragma unroll
    for (int i = 0; i < 4; i++) {
        int idx = tid + i * 512;
        int key = idx >> 4, d4 = idx & 15;
        cpa16(&dst[key * KSTRIDE + d4 * 4], &K[(size_t)(kt * 128 + key) * DK + d4 * 4]);
    }
}
__device__ __forceinline__ void stage_vt(const float* __restrict__ VT, int kt, float* dst) {
    int tid = threadIdx.x;
    #pragma unroll
    for (int i = 0; i < 4; i++) {
        int idx = tid + i * 512;          // 2048 chunks = 64 d-rows x 32
        int d = idx >> 5, c4 = idx & 31;
        cpa16(&dst[d * VTSTRIDE + c4 * 4], &VT[(size_t)d * Ss + kt * 128 + c4 * 4]);
    }
}

__global__ void __launch_bounds__(512, 1) attn_kernel(float* __restrict__ d_out) {
    extern __shared__ float smem[];
    float* sK0 = smem;
    float* sK1 = smem + SK_ELEMS;
    float* sVT0 = smem;                    // pass 2 aliases pass-1 K buffers
    float* sVT1 = smem + SVT_ELEMS;
    __shared__ float sred[16][16];
    __shared__ float sinvs[128];

    int qb = blockIdx.x, h = blockIdx.y, b = blockIdx.z;
    const float* Q  = g_qkvh[0] + (size_t)(b * Hh + h) * Ss * DK;
    const float* K  = g_qkvh[1] + (size_t)(b * Hh + h) * Ss * DK;
    const float* VT = g_vt      + (size_t)(b * Hh + h) * DK * Ss;
    int q0 = qb * 128;

    int tid = threadIdx.x;
    int lane = tid & 31, w = tid >> 5;
    int g = lane >> 2, t = lane & 3;
    int wq = w >> 1, wk2 = w & 1;
    const float scale = 0.125f;

    // Q fragments (k-lane remap) via float2 loads
    uint32_t qa[8][4];
    {
        const float* Qb = Q + (size_t)(q0 + wq * 16) * DK;
        #pragma unroll
        for (int ks = 0; ks < 8; ks++) {
            int c = ks * 8 + 2 * t;
            float2 lo = *(const float2*)&Qb[g * DK + c];
            float2 hi = *(const float2*)&Qb[(g + 8) * DK + c];
            qa[ks][0] = __float_as_uint(lo.x);
            qa[ks][1] = __float_as_uint(hi.x);
            qa[ks][2] = __float_as_uint(lo.y);
            qa[ks][3] = __float_as_uint(hi.y);
        }
    }

    // fragment-ordered bias / e bases
    const float4* b2 = (const float4*)g_bias2 + ((size_t)(qb * 16) * 16 + w) * 256 + lane;
    uint2* ep = g_e + (size_t)(b * Hh + h) * (Ss * (size_t)Ss / 4)
              + ((size_t)(qb * 16) * 16 + w) * 256 + lane;

    // ================= PASS 1: QK + exp -> fp16 e + row sums =================
    float2 rsum = make_float2(0.f, 0.f);
    stage_k(K, 0, sK0);
    CP_COMMIT();

    for (int kt = 0; kt < 16; kt++) {
        if (kt < 15) {
            __syncthreads();
            stage_k(K, kt + 1, (kt & 1) ? sK0 : sK1);
            CP_COMMIT();
            cp_wait<1>();
        } else {
            cp_wait<0>();
        }
        __syncthreads();

        const float* cK = (kt & 1) ? sK1 : sK0;
        const float* kbase = &cK[(wk2 * 64 + g) * KSTRIDE + 2 * t];
        #pragma unroll
        for (int j = 0; j < 8; j++) {
            float4 acc = make_float4(0.f, 0.f, 0.f, 0.f);
            const float* kp = kbase + j * 8 * KSTRIDE;
            #pragma unroll
            for (int ks = 0; ks < 8; ks++) {
                float2 bb = *(const float2*)&kp[ks * 8];
                mma_tf32(acc, qa[ks], __float_as_uint(bb.x), __float_as_uint(bb.y));
            }
            float4 bf = b2[kt * 4096 + j * 32];
            float e0 = __expf(fmaf(acc.x, scale, bf.x));
            float e1 = __expf(fmaf(acc.y, scale, bf.y));
            float e2 = __expf(fmaf(acc.z, scale, bf.z));
            float e3 = __expf(fmaf(acc.w, scale, bf.w));
            rsum.x += e0 + e1;
            rsum.y += e2 + e3;
            __half2 h01 = __floats2half2_rn(e0, e1);
            __half2 h23 = __floats2half2_rn(e2, e3);
            uint2 pk;
            pk.x = *(uint32_t*)&h01;
            pk.y = *(uint32_t*)&h23;
            ep[kt * 4096 + j * 32] = pk;
        }
    }

    // reduce row sums: over t lanes, then over wk2 halves
    rsum.x += __shfl_xor_sync(FULLM, rsum.x, 1);
    rsum.x += __shfl_xor_sync(FULLM, rsum.x, 2);
    rsum.y += __shfl_xor_sync(FULLM, rsum.y, 1);
    rsum.y += __shfl_xor_sync(FULLM, rsum.y, 2);
    if (t == 0) {
        sred[w][g] = rsum.x;
        sred[w][g + 8] = rsum.y;
    }
    __syncthreads();
    if (tid < 128) {
        int wqr = tid >> 4, rr = tid & 15;
        sinvs[tid] = 1.f / (sred[wqr * 2][rr] + sred[wqr * 2 + 1][rr]);
    }
    __syncthreads();
    float invx = sinvs[wq * 16 + g];
    float invy = sinvs[wq * 16 + g + 8];

    // ================= PASS 2: read e, normalize, write attn, PV =================
    float* attnp = d_out + (size_t)BS * Dd
                 + ((size_t)((b * Hh + h) * Ss) + q0 + wq * 16) * Ss;

    float4 oacc[8];
    #pragma unroll
    for (int j = 0; j < 8; j++) oacc[j] = make_float4(0.f, 0.f, 0.f, 0.f);

    stage_vt(VT, 0, sVT0);
    CP_COMMIT();

    for (int kt = 0; kt < 16; kt++) {
        if (kt < 15) {
            __syncthreads();
            stage_vt(VT, kt + 1, (kt & 1) ? sVT0 : sVT1);
            CP_COMMIT();
            cp_wait<1>();
        } else {
            cp_wait<0>();
        }
        __syncthreads();

        const float* cV = (kt & 1) ? sVT1 : sVT0;
        const float* vbase = &cV[(size_t)g * VTSTRIDE + wk2 * 64 + 2 * t];

        #pragma unroll
        for (int j = 0; j < 8; j++) {
            uint2 pk = ep[kt * 4096 + j * 32];
            __half2 h01 = *(__half2*)&pk.x;
            __half2 h23 = *(__half2*)&pk.y;
            float2 f0 = __half22float2(h01);
            float2 f1 = __half22float2(h23);
            float4 pv;
            pv.x = f0.x * invx; pv.y = f0.y * invx;
            pv.z = f1.x * invy; pv.w = f1.y * invy;

            int gc = kt * 128 + wk2 * 64 + j * 8 + 2 * t;
            *(float2*)&attnp[(size_t)g * Ss + gc] = make_float2(pv.x, pv.y);
            *(float2*)&attnp[(size_t)(g + 8) * Ss + gc] = make_float2(pv.z, pv.w);

            pv.x = rnd_tf32(pv.x); pv.y = rnd_tf32(pv.y);
            pv.z = rnd_tf32(pv.z); pv.w = rnd_tf32(pv.w);

            // PV A-frag via k-lane remap: {x, z, y, w}. No shuffles.
            uint32_t A[4];
            A[0] = __float_as_uint(pv.x);
            A[1] = __float_as_uint(pv.z);
            A[2] = __float_as_uint(pv.y);
            A[3] = __float_as_uint(pv.w);

            // B-frags from transposed V: adjacent keys -> LDS.64
            const float* vp = vbase + j * 8;
            #pragma unroll
            for (int jj = 0; jj < 8; jj++) {
                float2 bb = *(const float2*)&vp[(size_t)jj * 8 * VTSTRIDE];
                mma_tf32(oacc[jj], A, __float_as_uint(bb.x), __float_as_uint(bb.y));
            }
        }
    }

    // ---- combine wk2 halves via smem (alias staging buffers), write g_x ----
    __syncthreads();
    float* sacc = smem;   // 8 wq * 8 jj * 128 floats = 8192 floats
    if (wk2 == 1) {
        float* dst = &sacc[(wq * 8) * 128 + lane * 4];
        #pragma unroll
        for (int jj = 0; jj < 8; jj++) *(float4*)&dst[jj * 128] = oacc[jj];
    }
    __syncthreads();
    if (wk2 == 0) {
        const float* srcp = &sacc[(wq * 8) * 128 + lane * 4];
        #pragma unroll
        for (int jj = 0; jj < 8; jj++) {
            float4 o2 = *(const float4*)&srcp[jj * 128];
            float4 o = oacc[jj];
            o.x += o2.x; o.y += o2.y; o.z += o2.z; o.w += o2.w;
            int row0 = b * Ss + q0 + wq * 16 + g;
            int col = h * DK + jj * 8 + 2 * t;
            float2 r0, r1;
            r0.x = rnd_tf32(o.x); r0.y = rnd_tf32(o.y);
            r1.x = rnd_tf32(o.z); r1.y = rnd_tf32(o.w);
            *(float2*)&g_x[(size_t)row0 * Dd + col] = r0;
            *(float2*)&g_x[(size_t)(row0 + 8) * Dd + col] = r1;
        }
    }
}

// ---------------- launch ----------------
extern "C" void kernel_launch(void* const* d_in, const int* in_sizes, int n_in,
                              void* d_out, int out_size) {
    const float* q    = (const float*)d_in[0];
    const float* k    = (const float*)d_in[1];
    const float* v    = (const float*)d_in[2];
    const int*   mask = (const int*)  d_in[3];
    const float* pos  = (const float*)d_in[4];
    const float* ln_g = (const float*)d_in[5];
    const float* ln_b = (const float*)d_in[6];
    const float* wq   = (const float*)d_in[7];
    const float* bq   = (const float*)d_in[8];
    const float* wk   = (const float*)d_in[9];
    const float* bk   = (const float*)d_in[10];
    const float* wv   = (const float*)d_in[11];
    const float* bv   = (const float*)d_in[12];
    const float* wo   = (const float*)d_in[13];
    const float* bo   = (const float*)d_in[14];
    const float* ls   = (const float*)d_in[15];
    float* out = (float*)d_out;

    cudaFuncSetAttribute(attn_kernel, cudaFuncAttributeMaxDynamicSharedMemorySize,
                         ATTN_SMEM_BYTES);

    bias2_kernel<<<1024, 1024>>>(pos, mask);
    ln_kernel<<<dim3(BS, 3), 256>>>(q, k, v, ln_g, ln_b);
    wt_kernel<<<dim3(16, 16, 4), 256>>>(wq, wk, wv, wo);
    proj_qkv_kernel<<<dim3(BS / 64, Dd / 64, 3), 256>>>(bq, bk, bv);
    attn_kernel<<<dim3(Ss / 128, Hh, Bb), 512, ATTN_SMEM_BYTES>>>(out);
    proj_out_kernel<<<dim3(BS / 64, Dd / 64), 256>>>(bo, ls, out);
}

// round 14
// speedup vs baseline: 1.1913x; 1.1913x over previous
#include <cuda_runtime.h>
#include <math.h>
#include <stdint.h>

#define Bb 4
#define Ss 2048
#define Dd 512
#define Hh 8
#define DK 64
#define BS (Bb*Ss)          // 8192 rows
#define LN_EPS 1e-5f
#define NEG_BIG (-1e30f)

// ---------------- scratch (static device globals; no allocation) ----------------
__device__ float g_xn[3][(size_t)BS*Dd];                 // normalized q,k,v (tf32-rounded)
__device__ float g_qkvh[2][(size_t)Bb*Hh*Ss*DK];         // head-major Q,K (tf32-rounded)
__device__ float g_vt[(size_t)Bb*Hh*DK*Ss];              // V transposed per (b,h): [d][key]
__device__ float g_x[(size_t)BS*Dd];                     // attention output (tf32-rounded)
__device__ float g_wt[4][(size_t)Dd*Dd];                 // W^T, tf32-rounded: [n][k]
__device__ float g_bias2[(size_t)Ss*Ss];                 // bias in mma-fragment order (16.8 MB)

// ---------------- helpers ----------------
__device__ __forceinline__ uint32_t f2tf32(float x) {
    uint32_t r;
    asm volatile("cvt.rna.tf32.f32 %0, %1;" : "=r"(r) : "f"(x));
    return r;
}
__device__ __forceinline__ float rnd_tf32(float x) { return __uint_as_float(f2tf32(x)); }

__device__ __forceinline__ void mma_tf32(float4& d, const uint32_t a[4],
                                         uint32_t b0, uint32_t b1) {
    asm volatile(
        "mma.sync.aligned.m16n8k8.row.col.f32.tf32.tf32.f32 "
        "{%0,%1,%2,%3}, {%4,%5,%6,%7}, {%8,%9}, {%0,%1,%2,%3};\n"
        : "+f"(d.x), "+f"(d.y), "+f"(d.z), "+f"(d.w)
        : "r"(a[0]), "r"(a[1]), "r"(a[2]), "r"(a[3]), "r"(b0), "r"(b1));
}

__device__ __forceinline__ void cpa16(float* s, const float* g) {
    uint32_t sa = (uint32_t)__cvta_generic_to_shared(s);
    asm volatile("cp.async.ca.shared.global [%0], [%1], 16;\n" :: "r"(sa), "l"(g));
}
#define CP_COMMIT() asm volatile("cp.async.commit_group;\n")
template<int N> __device__ __forceinline__ void cp_wait() {
    asm volatile("cp.async.wait_group %0;\n" :: "n"(N));
}

// ---------------- Kernel 0: pack mask+pos into mma-fragment-ordered bias ----------------
__global__ void __launch_bounds__(1024) bias2_kernel(
    const float* __restrict__ pos, const int* __restrict__ mask) {
    int idx = blockIdx.x * 1024 + threadIdx.x;      // 0 .. 1,048,575
    int lane = idx & 31;
    int j    = (idx >> 5) & 7;
    int w    = (idx >> 8) & 15;
    int kt   = (idx >> 12) & 15;
    int qt   = idx >> 16;                            // 0..15
    int g = lane >> 2, t = lane & 3;
    int wq = w >> 1, wk2 = w & 1;
    int q = qt * 128 + wq * 16 + g;
    int c = kt * 128 + wk2 * 64 + j * 8 + 2 * t;
    const float* p0 = &pos[q * Ss + c];
    const float* p1 = &pos[(q + 8) * Ss + c];
    const int*   m0 = &mask[q * Ss + c];
    const int*   m1 = &mask[(q + 8) * Ss + c];
    float4 o;
    o.x = m0[0] ? p0[0] : NEG_BIG;
    o.y = m0[1] ? p0[1] : NEG_BIG;
    o.z = m1[0] ? p1[0] : NEG_BIG;
    o.w = m1[1] ? p1[1] : NEG_BIG;
    ((float4*)g_bias2)[idx] = o;
}

// ---------------- Kernel 1: LayerNorm (tf32-rounded output) ----------------
__global__ void ln_kernel(const float* __restrict__ q, const float* __restrict__ k,
                          const float* __restrict__ v, const float* __restrict__ g,
                          const float* __restrict__ b) {
    int row = blockIdx.x;
    int which = blockIdx.y;
    const float* xs = which == 0 ? q : (which == 1 ? k : v);
    const float* x = xs + (size_t)row * Dd;
    float* y = g_xn[which] + (size_t)row * Dd;
    int t = threadIdx.x;

    float v0 = x[t], v1 = x[t + 256];
    float s = v0 + v1, s2 = v0 * v0 + v1 * v1;

    __shared__ float rs[8], rs2[8];
    #pragma unroll
    for (int o = 16; o; o >>= 1) {
        s  += __shfl_xor_sync(0xFFFFFFFFu, s,  o);
        s2 += __shfl_xor_sync(0xFFFFFFFFu, s2, o);
    }
    if ((t & 31) == 0) { rs[t >> 5] = s; rs2[t >> 5] = s2; }
    __syncthreads();
    __shared__ float smu, sinv;
    if (t == 0) {
        float S = 0.f, S2 = 0.f;
        #pragma unroll
        for (int i = 0; i < 8; i++) { S += rs[i]; S2 += rs2[i]; }
        float mu = S * (1.f / 512.f);
        float var = S2 * (1.f / 512.f) - mu * mu;
        smu = mu; sinv = rsqrtf(var + LN_EPS);
    }
    __syncthreads();
    float mu = smu, inv = sinv;
    y[t]       = rnd_tf32((v0 - mu) * inv * g[t]       + b[t]);
    y[t + 256] = rnd_tf32((v1 - mu) * inv * g[t + 256] + b[t + 256]);
}

// ---------------- Kernel 1b: weight transpose + tf32 round ----------------
__global__ void wt_kernel(const float* __restrict__ wq, const float* __restrict__ wk,
                          const float* __restrict__ wv, const float* __restrict__ wo) {
    __shared__ float tile[32][33];
    int z = blockIdx.z;
    const float* W = z == 0 ? wq : (z == 1 ? wk : (z == 2 ? wv : wo));
    int k0 = blockIdx.x * 32, n0 = blockIdx.y * 32;
    int c = threadIdx.x & 31, r0 = threadIdx.x >> 5;
    #pragma unroll
    for (int i = 0; i < 4; i++) {
        int r = r0 + i * 8;
        tile[r][c] = W[(size_t)(k0 + r) * Dd + n0 + c];
    }
    __syncthreads();
    #pragma unroll
    for (int i = 0; i < 4; i++) {
        int r = r0 + i * 8;
        g_wt[z][(size_t)(n0 + r) * Dd + k0 + c] = rnd_tf32(tile[c][r]);
    }
}

// ---------------- tf32 GEMM tile core (BM=64, BN=64, BK=32, cp.async 2-stage) ----------------
#define GSTG 2560   // one stage: 64 rows * 40

__device__ __forceinline__ void gemm_load_stage(
    const float* __restrict__ A, const float* __restrict__ Bt,
    int m0, int n0, int k0, float* sA, float* sB) {
    int tid = threadIdx.x;
    #pragma unroll
    for (int i = 0; i < 2; i++) {
        int idx = tid + i * 256;
        int m = idx >> 3, c = idx & 7;
        cpa16(&sA[m * 40 + c * 4], &A[(size_t)(m0 + m) * Dd + k0 + c * 4]);
    }
    #pragma unroll
    for (int i = 0; i < 2; i++) {
        int idx = tid + i * 256;
        int n = idx >> 3, c = idx & 7;
        cpa16(&sB[n * 40 + c * 4], &Bt[(size_t)(n0 + n) * Dd + k0 + c * 4]);
    }
}

__device__ __forceinline__ void gemm_tile_tf32(
    const float* __restrict__ A, const float* __restrict__ Bt,
    int m0, int n0, float4 acc[2][2], float* sA, float* sB) {
    int tid = threadIdx.x;
    int lane = tid & 31, w = tid >> 5;
    int g = lane >> 2, t = lane & 3;
    int wm = w >> 2, wn = w & 3;
    #pragma unroll
    for (int i = 0; i < 2; i++)
        #pragma unroll
        for (int j = 0; j < 2; j++) acc[i][j] = make_float4(0.f, 0.f, 0.f, 0.f);

    gemm_load_stage(A, Bt, m0, n0, 0, sA, sB);
    CP_COMMIT();

    for (int it = 0; it < 16; it++) {
        if (it < 15) {
            int s = (it + 1) & 1;
            gemm_load_stage(A, Bt, m0, n0, (it + 1) * 32, sA + s * GSTG, sB + s * GSTG);
            CP_COMMIT();
            cp_wait<1>();
        } else {
            cp_wait<0>();
        }
        __syncthreads();

        const float* cA = sA + (it & 1) * GSTG;
        const float* cB = sB + (it & 1) * GSTG;
        #pragma unroll
        for (int ks = 0; ks < 4; ks++) {
            int kk = ks * 8;
            uint32_t a[2][4];
            #pragma unroll
            for (int mi = 0; mi < 2; mi++) {
                const float* ap  = &cA[(wm * 32 + mi * 16 + g) * 40 + kk + 2 * t];
                const float* ap2 = ap + 8 * 40;
                float2 lo = *(const float2*)ap;
                float2 hi = *(const float2*)ap2;
                a[mi][0] = __float_as_uint(lo.x);
                a[mi][1] = __float_as_uint(hi.x);
                a[mi][2] = __float_as_uint(lo.y);
                a[mi][3] = __float_as_uint(hi.y);
            }
            #pragma unroll
            for (int nj = 0; nj < 2; nj++) {
                const float* bp = &cB[(wn * 16 + nj * 8 + g) * 40 + kk + 2 * t];
                float2 bb = *(const float2*)bp;
                uint32_t b0 = __float_as_uint(bb.x);
                uint32_t b1 = __float_as_uint(bb.y);
                mma_tf32(acc[0][nj], a[0], b0, b1);
                mma_tf32(acc[1][nj], a[1], b0, b1);
            }
        }
        __syncthreads();
    }
}

// ---------------- Kernel 2: QKV projection (Q,K head-major; V transposed) ----------------
__global__ void __launch_bounds__(256) proj_qkv_kernel(
    const float* __restrict__ bq, const float* __restrict__ bk, const float* __restrict__ bv) {
    __shared__ float sA[2 * GSTG];
    __shared__ float sB[2 * GSTG];
    int z = blockIdx.z;
    const float* bias = z == 0 ? bq : (z == 1 ? bk : bv);
    int m0 = blockIdx.x * 64, n0 = blockIdx.y * 64;

    float4 acc[2][2];
    gemm_tile_tf32(g_xn[z], g_wt[z], m0, n0, acc, sA, sB);

    int lane = threadIdx.x & 31, w = threadIdx.x >> 5;
    int g = lane >> 2, t = lane & 3;
    int wm = w >> 2, wn = w & 3;
    #pragma unroll
    for (int mi = 0; mi < 2; mi++) {
        #pragma unroll
        for (int nj = 0; nj < 2; nj++) {
            int n = n0 + wn * 16 + nj * 8 + 2 * t;
            int hh = n >> 6, dd = n & 63;
            float b0 = bias[n], b1 = bias[n + 1];
            #pragma unroll
            for (int r = 0; r < 2; r++) {
                int m = m0 + wm * 32 + mi * 16 + g + r * 8;
                int bidx = m >> 11, srow = m & 2047;
                float2 val;
                if (r == 0) { val.x = acc[mi][nj].x + b0; val.y = acc[mi][nj].y + b1; }
                else        { val.x = acc[mi][nj].z + b0; val.y = acc[mi][nj].w + b1; }
                val.x = rnd_tf32(val.x); val.y = rnd_tf32(val.y);
                if (z == 2) {
                    // V transposed: VT[(bh)*64 + d][key]
                    float* VT = g_vt + (size_t)(bidx * Hh + hh) * DK * Ss;
                    VT[(size_t)dd * Ss + srow]       = val.x;
                    VT[(size_t)(dd + 1) * Ss + srow] = val.y;
                } else {
                    float* out = g_qkvh[z];
                    *(float2*)&out[(((size_t)(bidx * Hh + hh) * Ss + srow) * DK) + dd] = val;
                }
            }
        }
    }
}

// ---------------- Kernel 4: output projection ----------------
__global__ void __launch_bounds__(256) proj_out_kernel(
    const float* __restrict__ bo, const float* __restrict__ ls, float* __restrict__ Cout) {
    __shared__ float sA[2 * GSTG];
    __shared__ float sB[2 * GSTG];
    int m0 = blockIdx.x * 64, n0 = blockIdx.y * 64;

    float4 acc[2][2];
    gemm_tile_tf32(g_x, g_wt[3], m0, n0, acc, sA, sB);

    int lane = threadIdx.x & 31, w = threadIdx.x >> 5;
    int g = lane >> 2, t = lane & 3;
    int wm = w >> 2, wn = w & 3;
    #pragma unroll
    for (int mi = 0; mi < 2; mi++) {
        #pragma unroll
        for (int nj = 0; nj < 2; nj++) {
            int n = n0 + wn * 16 + nj * 8 + 2 * t;
            float b0 = bo[n], b1 = bo[n + 1];
            float l0 = ls[n], l1 = ls[n + 1];
            #pragma unroll
            for (int r = 0; r < 2; r++) {
                int m = m0 + wm * 32 + mi * 16 + g + r * 8;
                float2 val;
                if (r == 0) { val.x = (acc[mi][nj].x + b0) * l0; val.y = (acc[mi][nj].y + b1) * l1; }
                else        { val.x = (acc[mi][nj].z + b0) * l0; val.y = (acc[mi][nj].w + b1) * l1; }
                *(float2*)&Cout[(size_t)m * Dd + n] = val;
            }
        }
    }
}

// ---------------- Kernel 3: attention — TQ=128, two-pass, VT for PV (LDS.64) ----------------
#define KSTRIDE 72
#define VTSTRIDE 136
#define SK_ELEMS (128 * KSTRIDE)      // 9216
#define SVT_ELEMS (64 * VTSTRIDE)     // 8704
#define ATTN_SMEM_BYTES ((2 * SK_ELEMS + 2 * SVT_ELEMS) * 4)   // 143,360
#define FULLM 0xFFFFFFFFu

__device__ __forceinline__ void stage_k(const float* __restrict__ K, int kt, float* dst) {
    int tid = threadIdx.x;
    #pragma unroll
    for (int i = 0; i < 4; i++) {
        int idx = tid + i * 512;
        int key = idx >> 4, d4 = idx & 15;
        cpa16(&dst[key * KSTRIDE + d4 * 4], &K[(size_t)(kt * 128 + key) * DK + d4 * 4]);
    }
}
__device__ __forceinline__ void stage_vt(const float* __restrict__ VT, int kt, float* dst) {
    int tid = threadIdx.x;
    #pragma unroll
    for (int i = 0; i < 4; i++) {
        int idx = tid + i * 512;          // 2048 chunks = 64 d-rows x 32
        int d = idx >> 5, c4 = idx & 31;
        cpa16(&dst[d * VTSTRIDE + c4 * 4], &VT[(size_t)d * Ss + kt * 128 + c4 * 4]);
    }
}

__global__ void __launch_bounds__(512, 1) attn_kernel(float* __restrict__ d_out) {
    extern __shared__ float smem[];
    float* sK0 = smem;
    float* sK1 = smem + SK_ELEMS;
    float* sVT0 = smem + 2 * SK_ELEMS;
    float* sVT1 = sVT0 + SVT_ELEMS;
    __shared__ float sred[16][16];
    __shared__ float sinvs[128];

    int qb = blockIdx.x, h = blockIdx.y, b = blockIdx.z;
    const float* Q  = g_qkvh[0] + (size_t)(b * Hh + h) * Ss * DK;
    const float* K  = g_qkvh[1] + (size_t)(b * Hh + h) * Ss * DK;
    const float* VT = g_vt      + (size_t)(b * Hh + h) * DK * Ss;
    int q0 = qb * 128;

    int tid = threadIdx.x;
    int lane = tid & 31, w = tid >> 5;
    int g = lane >> 2, t = lane & 3;
    int wq = w >> 1, wk2 = w & 1;
    const float scale = 0.125f;

    // Q fragments (k-lane remap) via float2 loads
    uint32_t qa[8][4];
    {
        const float* Qb = Q + (size_t)(q0 + wq * 16) * DK;
        #pragma unroll
        for (int ks = 0; ks < 8; ks++) {
            int c = ks * 8 + 2 * t;
            float2 lo = *(const float2*)&Qb[g * DK + c];
            float2 hi = *(const float2*)&Qb[(g + 8) * DK + c];
            qa[ks][0] = __float_as_uint(lo.x);
            qa[ks][1] = __float_as_uint(hi.x);
            qa[ks][2] = __float_as_uint(lo.y);
            qa[ks][3] = __float_as_uint(hi.y);
        }
    }

    // fragment-ordered bias base: ((qb*16 + kt)*16 + w)*256 + j*32 + lane
    const float4* b2 = (const float4*)g_bias2 + ((size_t)(qb * 16) * 16 + w) * 256 + lane;

    // ================= PASS 1: row sums =================
    float2 rsum = make_float2(0.f, 0.f);
    stage_k(K, 0, sK0);
    CP_COMMIT();

    for (int kt = 0; kt < 16; kt++) {
        if (kt < 15) {
            __syncthreads();
            stage_k(K, kt + 1, (kt & 1) ? sK0 : sK1);
            CP_COMMIT();
            cp_wait<1>();
        } else {
            cp_wait<0>();
        }
        __syncthreads();

        const float* cK = (kt & 1) ? sK1 : sK0;
        const float* kbase = &cK[(wk2 * 64 + g) * KSTRIDE + 2 * t];
        #pragma unroll
        for (int j = 0; j < 8; j++) {
            float4 acc = make_float4(0.f, 0.f, 0.f, 0.f);
            const float* kp = kbase + j * 8 * KSTRIDE;
            #pragma unroll
            for (int ks = 0; ks < 8; ks++) {
                float2 bb = *(const float2*)&kp[ks * 8];
                mma_tf32(acc, qa[ks], __float_as_uint(bb.x), __float_as_uint(bb.y));
            }
            float4 bf = b2[kt * 4096 + j * 32];
            float e0 = __expf(fmaf(acc.x, scale, bf.x));
            float e1 = __expf(fmaf(acc.y, scale, bf.y));
            float e2 = __expf(fmaf(acc.z, scale, bf.z));
            float e3 = __expf(fmaf(acc.w, scale, bf.w));
            rsum.x += e0 + e1;
            rsum.y += e2 + e3;
        }
    }

    // reduce row sums: over t lanes, then over wk2 halves
    rsum.x += __shfl_xor_sync(FULLM, rsum.x, 1);
    rsum.x += __shfl_xor_sync(FULLM, rsum.x, 2);
    rsum.y += __shfl_xor_sync(FULLM, rsum.y, 1);
    rsum.y += __shfl_xor_sync(FULLM, rsum.y, 2);
    if (t == 0) {
        sred[w][g] = rsum.x;
        sred[w][g + 8] = rsum.y;
    }
    __syncthreads();
    if (tid < 128) {
        int wqr = tid >> 4, rr = tid & 15;
        sinvs[tid] = 1.f / (sred[wqr * 2][rr] + sred[wqr * 2 + 1][rr]);
    }
    __syncthreads();
    float invx = sinvs[wq * 16 + g];
    float invy = sinvs[wq * 16 + g + 8];

    // ================= PASS 2: attn write + PV (VT, LDS.64 B-frags) =================
    float* attnp = d_out + (size_t)BS * Dd
                 + ((size_t)((b * Hh + h) * Ss) + q0 + wq * 16) * Ss;

    float4 oacc[8];
    #pragma unroll
    for (int j = 0; j < 8; j++) oacc[j] = make_float4(0.f, 0.f, 0.f, 0.f);

    stage_k(K, 0, sK0);
    stage_vt(VT, 0, sVT0);
    CP_COMMIT();

    for (int kt = 0; kt < 16; kt++) {
        if (kt < 15) {
            __syncthreads();
            stage_k(K, kt + 1, (kt & 1) ? sK0 : sK1);
            stage_vt(VT, kt + 1, (kt & 1) ? sVT0 : sVT1);
            CP_COMMIT();
            cp_wait<1>();
        } else {
            cp_wait<0>();
        }
        __syncthreads();

        const float* cK = (kt & 1) ? sK1 : sK0;
        const float* cV = (kt & 1) ? sVT1 : sVT0;
        const float* kbase = &cK[(wk2 * 64 + g) * KSTRIDE + 2 * t];

        #pragma unroll
        for (int j = 0; j < 8; j++) {
            float4 acc = make_float4(0.f, 0.f, 0.f, 0.f);
            const float* kp = kbase + j * 8 * KSTRIDE;
            #pragma unroll
            for (int ks = 0; ks < 8; ks++) {
                float2 bb = *(const float2*)&kp[ks * 8];
                mma_tf32(acc, qa[ks], __float_as_uint(bb.x), __float_as_uint(bb.y));
            }
            float4 bf = b2[kt * 4096 + j * 32];
            float4 pv;
            pv.x = __expf(fmaf(acc.x, scale, bf.x)) * invx;
            pv.y = __expf(fmaf(acc.y, scale, bf.y)) * invx;
            pv.z = __expf(fmaf(acc.z, scale, bf.z)) * invy;
            pv.w = __expf(fmaf(acc.w, scale, bf.w)) * invy;

            int gc = kt * 128 + wk2 * 64 + j * 8 + 2 * t;
            *(float2*)&attnp[(size_t)g * Ss + gc] = make_float2(pv.x, pv.y);
            *(float2*)&attnp[(size_t)(g + 8) * Ss + gc] = make_float2(pv.z, pv.w);

            pv.x = rnd_tf32(pv.x); pv.y = rnd_tf32(pv.y);
            pv.z = rnd_tf32(pv.z); pv.w = rnd_tf32(pv.w);

            // PV A-frag via k-lane remap: {x, z, y, w}. No shuffles.
            uint32_t A[4];
            A[0] = __float_as_uint(pv.x);
            A[1] = __float_as_uint(pv.z);
            A[2] = __float_as_uint(pv.y);
            A[3] = __float_as_uint(pv.w);

            // B-frags from transposed V: adjacent keys -> one LDS.64 each
            const float* vp = &cV[wk2 * 64 + j * 8 + 2 * t + (size_t)g * VTSTRIDE];
            #pragma unroll
            for (int jj = 0; jj < 8; jj++) {
                float2 bb = *(const float2*)&vp[(size_t)jj * 8 * VTSTRIDE];
                mma_tf32(oacc[jj], A, __float_as_uint(bb.x), __float_as_uint(bb.y));
            }
        }
    }

    // ---- combine wk2 halves via smem (alias staging buffers), write g_x ----
    __syncthreads();
    float* sacc = smem;   // 8 wq * 8 jj * 128 floats = 8192 floats
    if (wk2 == 1) {
        float* dst = &sacc[(wq * 8) * 128 + lane * 4];
        #pragma unroll
        for (int jj = 0; jj < 8; jj++) *(float4*)&dst[jj * 128] = oacc[jj];
    }
    __syncthreads();
    if (wk2 == 0) {
        const float* srcp = &sacc[(wq * 8) * 128 + lane * 4];
        #pragma unroll
        for (int jj = 0; jj < 8; jj++) {
            float4 o2 = *(const float4*)&srcp[jj * 128];
            float4 o = oacc[jj];
            o.x += o2.x; o.y += o2.y; o.z += o2.z; o.w += o2.w;
            int row0 = b * Ss + q0 + wq * 16 + g;
            int col = h * DK + jj * 8 + 2 * t;
            float2 r0, r1;
            r0.x = rnd_tf32(o.x); r0.y = rnd_tf32(o.y);
            r1.x = rnd_tf32(o.z); r1.y = rnd_tf32(o.w);
            *(float2*)&g_x[(size_t)row0 * Dd + col] = r0;
            *(float2*)&g_x[(size_t)(row0 + 8) * Dd + col] = r1;
        }
    }
}

// ---------------- launch ----------------
extern "C" void kernel_launch(void* const* d_in, const int* in_sizes, int n_in,
                              void* d_out, int out_size) {
    const float* q    = (const float*)d_in[0];
    const float* k    = (const float*)d_in[1];
    const float* v    = (const float*)d_in[2];
    const int*   mask = (const int*)  d_in[3];
    const float* pos  = (const float*)d_in[4];
    const float* ln_g = (const float*)d_in[5];
    const float* ln_b = (const float*)d_in[6];
    const float* wq   = (const float*)d_in[7];
    const float* bq   = (const float*)d_in[8];
    const float* wk   = (const float*)d_in[9];
    const float* bk   = (const float*)d_in[10];
    const float* wv   = (const float*)d_in[11];
    const float* bv   = (const float*)d_in[12];
    const float* wo   = (const float*)d_in[13];
    const float* bo   = (const float*)d_in[14];
    const float* ls   = (const float*)d_in[15];
    float* out = (float*)d_out;

    cudaFuncSetAttribute(attn_kernel, cudaFuncAttributeMaxDynamicSharedMemorySize,
                         ATTN_SMEM_BYTES);

    bias2_kernel<<<1024, 1024>>>(pos, mask);
    ln_kernel<<<dim3(BS, 3), 256>>>(q, k, v, ln_g, ln_b);
    wt_kernel<<<dim3(16, 16, 4), 256>>>(wq, wk, wv, wo);
    proj_qkv_kernel<<<dim3(BS / 64, Dd / 64, 3), 256>>>(bq, bk, bv);
    attn_kernel<<<dim3(Ss / 128, Hh, Bb), 512, ATTN_SMEM_BYTES>>>(out);
    proj_out_kernel<<<dim3(BS / 64, Dd / 64), 256>>>(bo, ls, out);
}

// round 15
// speedup vs baseline: 1.5382x; 1.2912x over previous
#include <cuda_runtime.h>
#include <cuda_fp16.h>
#include <math.h>
#include <stdint.h>

#define Bb 4
#define Ss 2048
#define Dd 512
#define Hh 8
#define DK 64
#define BS (Bb*Ss)          // 8192 rows
#define LN_EPS 1e-5f
#define NEG_BIG (-1e30f)

// ---------------- scratch (static device globals; no allocation) ----------------
__device__ float  g_xn[3][(size_t)BS*Dd];                // normalized q,k,v (tf32-rounded)
__device__ __half2 g_qkh[2][(size_t)Bb*Hh*Ss*(DK/2)];    // Q,K fp16 head-major [s][d/2]
__device__ __half  g_vth[(size_t)Bb*Hh*DK*Ss];           // V fp16 transposed [d][key]
__device__ float  g_x[(size_t)BS*Dd];                    // attention output (tf32-rounded)
__device__ float  g_wt[4][(size_t)Dd*Dd];                // W^T, tf32-rounded: [n][k]
__device__ float  g_bias2[(size_t)Ss*Ss];                // bias in mma-fragment order

// ---------------- helpers ----------------
__device__ __forceinline__ uint32_t f2tf32(float x) {
    uint32_t r;
    asm volatile("cvt.rna.tf32.f32 %0, %1;" : "=r"(r) : "f"(x));
    return r;
}
__device__ __forceinline__ float rnd_tf32(float x) { return __uint_as_float(f2tf32(x)); }

__device__ __forceinline__ void mma_tf32(float4& d, const uint32_t a[4],
                                         uint32_t b0, uint32_t b1) {
    asm volatile(
        "mma.sync.aligned.m16n8k8.row.col.f32.tf32.tf32.f32 "
        "{%0,%1,%2,%3}, {%4,%5,%6,%7}, {%8,%9}, {%0,%1,%2,%3};\n"
        : "+f"(d.x), "+f"(d.y), "+f"(d.z), "+f"(d.w)
        : "r"(a[0]), "r"(a[1]), "r"(a[2]), "r"(a[3]), "r"(b0), "r"(b1));
}

__device__ __forceinline__ void mma_f16(float4& d, const uint32_t a[4],
                                        uint32_t b0, uint32_t b1) {
    asm volatile(
        "mma.sync.aligned.m16n8k16.row.col.f32.f16.f16.f32 "
        "{%0,%1,%2,%3}, {%4,%5,%6,%7}, {%8,%9}, {%0,%1,%2,%3};\n"
        : "+f"(d.x), "+f"(d.y), "+f"(d.z), "+f"(d.w)
        : "r"(a[0]), "r"(a[1]), "r"(a[2]), "r"(a[3]), "r"(b0), "r"(b1));
}

__device__ __forceinline__ void cpa16(void* s, const void* g) {
    uint32_t sa = (uint32_t)__cvta_generic_to_shared(s);
    asm volatile("cp.async.ca.shared.global [%0], [%1], 16;\n" :: "r"(sa), "l"(g));
}
#define CP_COMMIT() asm volatile("cp.async.commit_group;\n")
template<int N> __device__ __forceinline__ void cp_wait() {
    asm volatile("cp.async.wait_group %0;\n" :: "n"(N));
}

__device__ __forceinline__ uint32_t h2u(__half2 h) { return *(uint32_t*)&h; }

// ---------------- Kernel 0: pack mask+pos into mma-fragment-ordered bias ----------------
__global__ void __launch_bounds__(1024) bias2_kernel(
    const float* __restrict__ pos, const int* __restrict__ mask) {
    int idx = blockIdx.x * 1024 + threadIdx.x;      // 0 .. 1,048,575
    int lane = idx & 31;
    int j    = (idx >> 5) & 7;
    int w    = (idx >> 8) & 15;
    int kt   = (idx >> 12) & 15;
    int qt   = idx >> 16;                            // 0..15
    int g = lane >> 2, t = lane & 3;
    int wq = w >> 1, wk2 = w & 1;
    int q = qt * 128 + wq * 16 + g;
    int c = kt * 128 + wk2 * 64 + j * 8 + 2 * t;
    const float* p0 = &pos[q * Ss + c];
    const float* p1 = &pos[(q + 8) * Ss + c];
    const int*   m0 = &mask[q * Ss + c];
    const int*   m1 = &mask[(q + 8) * Ss + c];
    float4 o;
    o.x = m0[0] ? p0[0] : NEG_BIG;
    o.y = m0[1] ? p0[1] : NEG_BIG;
    o.z = m1[0] ? p1[0] : NEG_BIG;
    o.w = m1[1] ? p1[1] : NEG_BIG;
    ((float4*)g_bias2)[idx] = o;
}

// ---------------- Kernel 1: LayerNorm (tf32-rounded output) ----------------
__global__ void ln_kernel(const float* __restrict__ q, const float* __restrict__ k,
                          const float* __restrict__ v, const float* __restrict__ g,
                          const float* __restrict__ b) {
    int row = blockIdx.x;
    int which = blockIdx.y;
    const float* xs = which == 0 ? q : (which == 1 ? k : v);
    const float* x = xs + (size_t)row * Dd;
    float* y = g_xn[which] + (size_t)row * Dd;
    int t = threadIdx.x;

    float v0 = x[t], v1 = x[t + 256];
    float s = v0 + v1, s2 = v0 * v0 + v1 * v1;

    __shared__ float rs[8], rs2[8];
    #pragma unroll
    for (int o = 16; o; o >>= 1) {
        s  += __shfl_xor_sync(0xFFFFFFFFu, s,  o);
        s2 += __shfl_xor_sync(0xFFFFFFFFu, s2, o);
    }
    if ((t & 31) == 0) { rs[t >> 5] = s; rs2[t >> 5] = s2; }
    __syncthreads();
    __shared__ float smu, sinv;
    if (t == 0) {
        float S = 0.f, S2 = 0.f;
        #pragma unroll
        for (int i = 0; i < 8; i++) { S += rs[i]; S2 += rs2[i]; }
        float mu = S * (1.f / 512.f);
        float var = S2 * (1.f / 512.f) - mu * mu;
        smu = mu; sinv = rsqrtf(var + LN_EPS);
    }
    __syncthreads();
    float mu = smu, inv = sinv;
    y[t]       = rnd_tf32((v0 - mu) * inv * g[t]       + b[t]);
    y[t + 256] = rnd_tf32((v1 - mu) * inv * g[t + 256] + b[t + 256]);
}

// ---------------- Kernel 1b: weight transpose + tf32 round ----------------
__global__ void wt_kernel(const float* __restrict__ wq, const float* __restrict__ wk,
                          const float* __restrict__ wv, const float* __restrict__ wo) {
    __shared__ float tile[32][33];
    int z = blockIdx.z;
    const float* W = z == 0 ? wq : (z == 1 ? wk : (z == 2 ? wv : wo));
    int k0 = blockIdx.x * 32, n0 = blockIdx.y * 32;
    int c = threadIdx.x & 31, r0 = threadIdx.x >> 5;
    #pragma unroll
    for (int i = 0; i < 4; i++) {
        int r = r0 + i * 8;
        tile[r][c] = W[(size_t)(k0 + r) * Dd + n0 + c];
    }
    __syncthreads();
    #pragma unroll
    for (int i = 0; i < 4; i++) {
        int r = r0 + i * 8;
        g_wt[z][(size_t)(n0 + r) * Dd + k0 + c] = rnd_tf32(tile[c][r]);
    }
}

// ---------------- tf32 GEMM tile core (BM=64, BN=64, BK=32, cp.async 2-stage) ----------------
#define GSTG 2560   // one stage: 64 rows * 40

__device__ __forceinline__ void gemm_load_stage(
    const float* __restrict__ A, const float* __restrict__ Bt,
    int m0, int n0, int k0, float* sA, float* sB) {
    int tid = threadIdx.x;
    #pragma unroll
    for (int i = 0; i < 2; i++) {
        int idx = tid + i * 256;
        int m = idx >> 3, c = idx & 7;
        cpa16(&sA[m * 40 + c * 4], &A[(size_t)(m0 + m) * Dd + k0 + c * 4]);
    }
    #pragma unroll
    for (int i = 0; i < 2; i++) {
        int idx = tid + i * 256;
        int n = idx >> 3, c = idx & 7;
        cpa16(&sB[n * 40 + c * 4], &Bt[(size_t)(n0 + n) * Dd + k0 + c * 4]);
    }
}

__device__ __forceinline__ void gemm_tile_tf32(
    const float* __restrict__ A, const float* __restrict__ Bt,
    int m0, int n0, float4 acc[2][2], float* sA, float* sB) {
    int tid = threadIdx.x;
    int lane = tid & 31, w = tid >> 5;
    int g = lane >> 2, t = lane & 3;
    int wm = w >> 2, wn = w & 3;
    #pragma unroll
    for (int i = 0; i < 2; i++)
        #pragma unroll
        for (int j = 0; j < 2; j++) acc[i][j] = make_float4(0.f, 0.f, 0.f, 0.f);

    gemm_load_stage(A, Bt, m0, n0, 0, sA, sB);
    CP_COMMIT();

    for (int it = 0; it < 16; it++) {
        if (it < 15) {
            int s = (it + 1) & 1;
            gemm_load_stage(A, Bt, m0, n0, (it + 1) * 32, sA + s * GSTG, sB + s * GSTG);
            CP_COMMIT();
            cp_wait<1>();
        } else {
            cp_wait<0>();
        }
        __syncthreads();

        const float* cA = sA + (it & 1) * GSTG;
        const float* cB = sB + (it & 1) * GSTG;
        #pragma unroll
        for (int ks = 0; ks < 4; ks++) {
            int kk = ks * 8;
            uint32_t a[2][4];
            #pragma unroll
            for (int mi = 0; mi < 2; mi++) {
                const float* ap  = &cA[(wm * 32 + mi * 16 + g) * 40 + kk + 2 * t];
                const float* ap2 = ap + 8 * 40;
                float2 lo = *(const float2*)ap;
                float2 hi = *(const float2*)ap2;
                a[mi][0] = __float_as_uint(lo.x);
                a[mi][1] = __float_as_uint(hi.x);
                a[mi][2] = __float_as_uint(lo.y);
                a[mi][3] = __float_as_uint(hi.y);
            }
            #pragma unroll
            for (int nj = 0; nj < 2; nj++) {
                const float* bp = &cB[(wn * 16 + nj * 8 + g) * 40 + kk + 2 * t];
                float2 bb = *(const float2*)bp;
                uint32_t b0 = __float_as_uint(bb.x);
                uint32_t b1 = __float_as_uint(bb.y);
                mma_tf32(acc[0][nj], a[0], b0, b1);
                mma_tf32(acc[1][nj], a[1], b0, b1);
            }
        }
        __syncthreads();
    }
}

// ---------------- Kernel 2: QKV projection (Q,K fp16 head-major; V fp16 transposed) ----------------
__global__ void __launch_bounds__(256) proj_qkv_kernel(
    const float* __restrict__ bq, const float* __restrict__ bk, const float* __restrict__ bv) {
    __shared__ float sA[2 * GSTG];
    __shared__ float sB[2 * GSTG];
    int z = blockIdx.z;
    const float* bias = z == 0 ? bq : (z == 1 ? bk : bv);
    int m0 = blockIdx.x * 64, n0 = blockIdx.y * 64;

    float4 acc[2][2];
    gemm_tile_tf32(g_xn[z], g_wt[z], m0, n0, acc, sA, sB);

    int lane = threadIdx.x & 31, w = threadIdx.x >> 5;
    int g = lane >> 2, t = lane & 3;
    int wm = w >> 2, wn = w & 3;
    #pragma unroll
    for (int mi = 0; mi < 2; mi++) {
        #pragma unroll
        for (int nj = 0; nj < 2; nj++) {
            int n = n0 + wn * 16 + nj * 8 + 2 * t;
            int hh = n >> 6, dd = n & 63;
            float b0 = bias[n], b1 = bias[n + 1];
            #pragma unroll
            for (int r = 0; r < 2; r++) {
                int m = m0 + wm * 32 + mi * 16 + g + r * 8;
                int bidx = m >> 11, srow = m & 2047;
                float vx, vy;
                if (r == 0) { vx = acc[mi][nj].x + b0; vy = acc[mi][nj].y + b1; }
                else        { vx = acc[mi][nj].z + b0; vy = acc[mi][nj].w + b1; }
                if (z == 2) {
                    __half* VT = g_vth + (size_t)(bidx * Hh + hh) * DK * Ss;
                    VT[(size_t)dd * Ss + srow]       = __float2half_rn(vx);
                    VT[(size_t)(dd + 1) * Ss + srow] = __float2half_rn(vy);
                } else {
                    __half2* out = g_qkh[z] + ((size_t)(bidx * Hh + hh) * Ss + srow) * (DK / 2);
                    out[dd >> 1] = __floats2half2_rn(vx, vy);
                }
            }
        }
    }
}

// ---------------- Kernel 4: output projection ----------------
__global__ void __launch_bounds__(256) proj_out_kernel(
    const float* __restrict__ bo, const float* __restrict__ ls, float* __restrict__ Cout) {
    __shared__ float sA[2 * GSTG];
    __shared__ float sB[2 * GSTG];
    int m0 = blockIdx.x * 64, n0 = blockIdx.y * 64;

    float4 acc[2][2];
    gemm_tile_tf32(g_x, g_wt[3], m0, n0, acc, sA, sB);

    int lane = threadIdx.x & 31, w = threadIdx.x >> 5;
    int g = lane >> 2, t = lane & 3;
    int wm = w >> 2, wn = w & 3;
    #pragma unroll
    for (int mi = 0; mi < 2; mi++) {
        #pragma unroll
        for (int nj = 0; nj < 2; nj++) {
            int n = n0 + wn * 16 + nj * 8 + 2 * t;
            float b0 = bo[n], b1 = bo[n + 1];
            float l0 = ls[n], l1 = ls[n + 1];
            #pragma unroll
            for (int r = 0; r < 2; r++) {
                int m = m0 + wm * 32 + mi * 16 + g + r * 8;
                float2 val;
                if (r == 0) { val.x = (acc[mi][nj].x + b0) * l0; val.y = (acc[mi][nj].y + b1) * l1; }
                else        { val.x = (acc[mi][nj].z + b0) * l0; val.y = (acc[mi][nj].w + b1) * l1; }
                *(float2*)&Cout[(size_t)m * Dd + n] = val;
            }
        }
    }
}

// ---------------- Kernel 3: attention — TQ=128, two-pass, fp16 m16n8k16 ----------------
#define KH2S 36                         // half2 per K smem row (32 + 4 pad)
#define VTH2S 68                        // half2 per VT smem row (64 + 4 pad)
#define SKH_ELEMS (128 * KH2S)          // 4608 half2 = 18432 B
#define SVTH_ELEMS (64 * VTH2S)         // 4352 half2 = 17408 B
#define ATTN_SMEM_BYTES ((2 * SKH_ELEMS + 2 * SVTH_ELEMS) * 4)   // 71,680
#define FULLM 0xFFFFFFFFu

__device__ __forceinline__ void stage_kh(const __half2* __restrict__ Kg, int kt, __half2* dst) {
    int tid = threadIdx.x;
    #pragma unroll
    for (int i = 0; i < 2; i++) {
        int idx = tid + i * 512;            // 1024 chunks = 128 keys x 8 (16B = 4 half2)
        int key = idx >> 3, c = idx & 7;
        cpa16(&dst[key * KH2S + c * 4], &Kg[(size_t)(kt * 128 + key) * (DK / 2) + c * 4]);
    }
}
__device__ __forceinline__ void stage_vth(const __half* __restrict__ VTg, int kt, __half2* dst) {
    int tid = threadIdx.x;
    #pragma unroll
    for (int i = 0; i < 2; i++) {
        int idx = tid + i * 512;            // 1024 chunks = 64 d-rows x 16 (16B = 8 half)
        int d = idx >> 4, c = idx & 15;
        cpa16(&dst[d * VTH2S + c * 4], &VTg[(size_t)d * Ss + kt * 128 + c * 8]);
    }
}

__global__ void __launch_bounds__(512, 1) attn_kernel(float* __restrict__ d_out) {
    extern __shared__ __half2 smemh[];
    __half2* sK0 = smemh;
    __half2* sK1 = smemh + SKH_ELEMS;
    __half2* sV0 = smemh + 2 * SKH_ELEMS;
    __half2* sV1 = sV0 + SVTH_ELEMS;
    __shared__ float sred[16][16];
    __shared__ float sinvs[128];

    int qb = blockIdx.x, h = blockIdx.y, b = blockIdx.z;
    const __half2* Qg = g_qkh[0] + (size_t)(b * Hh + h) * Ss * (DK / 2);
    const __half2* Kg = g_qkh[1] + (size_t)(b * Hh + h) * Ss * (DK / 2);
    const __half*  VTg = g_vth   + (size_t)(b * Hh + h) * DK * Ss;
    int q0 = qb * 128;

    int tid = threadIdx.x;
    int lane = tid & 31, w = tid >> 5;
    int g = lane >> 2, t = lane & 3;
    int wq = w >> 1, wk2 = w & 1;
    const float scale = 0.125f;

    // Q fragments for m16n8k16: qa[ks][0]=(g, 2t,2t+1) qa[ks][1]=(g+8,..) qa[ks][2]=(g, 2t+8..) qa[ks][3]=(g+8,..)
    uint32_t qa[4][4];
    {
        const __half2* Qr0 = Qg + (size_t)(q0 + wq * 16 + g) * (DK / 2);
        const __half2* Qr1 = Qg + (size_t)(q0 + wq * 16 + g + 8) * (DK / 2);
        #pragma unroll
        for (int ks = 0; ks < 4; ks++) {
            qa[ks][0] = h2u(Qr0[8 * ks + t]);
            qa[ks][1] = h2u(Qr1[8 * ks + t]);
            qa[ks][2] = h2u(Qr0[8 * ks + t + 4]);
            qa[ks][3] = h2u(Qr1[8 * ks + t + 4]);
        }
    }

    // fragment-ordered bias base
    const float4* b2 = (const float4*)g_bias2 + ((size_t)(qb * 16) * 16 + w) * 256 + lane;

    // ================= PASS 1: row sums =================
    float2 rsum = make_float2(0.f, 0.f);
    stage_kh(Kg, 0, sK0);
    CP_COMMIT();

    for (int kt = 0; kt < 16; kt++) {
        if (kt < 15) {
            __syncthreads();
            stage_kh(Kg, kt + 1, (kt & 1) ? sK0 : sK1);
            CP_COMMIT();
            cp_wait<1>();
        } else {
            cp_wait<0>();
        }
        __syncthreads();

        const __half2* cK = (kt & 1) ? sK1 : sK0;
        #pragma unroll
        for (int j = 0; j < 8; j++) {
            float4 acc = make_float4(0.f, 0.f, 0.f, 0.f);
            const __half2* kp = &cK[(wk2 * 64 + j * 8 + g) * KH2S + t];
            #pragma unroll
            for (int ks = 0; ks < 4; ks++) {
                mma_f16(acc, qa[ks], h2u(kp[8 * ks]), h2u(kp[8 * ks + 4]));
            }
            float4 bf = b2[kt * 4096 + j * 32];
            float e0 = __expf(fmaf(acc.x, scale, bf.x));
            float e1 = __expf(fmaf(acc.y, scale, bf.y));
            float e2 = __expf(fmaf(acc.z, scale, bf.z));
            float e3 = __expf(fmaf(acc.w, scale, bf.w));
            rsum.x += e0 + e1;
            rsum.y += e2 + e3;
        }
    }

    // reduce row sums: over t lanes, then over wk2 halves
    rsum.x += __shfl_xor_sync(FULLM, rsum.x, 1);
    rsum.x += __shfl_xor_sync(FULLM, rsum.x, 2);
    rsum.y += __shfl_xor_sync(FULLM, rsum.y, 1);
    rsum.y += __shfl_xor_sync(FULLM, rsum.y, 2);
    if (t == 0) {
        sred[w][g] = rsum.x;
        sred[w][g + 8] = rsum.y;
    }
    __syncthreads();
    if (tid < 128) {
        int wqr = tid >> 4, rr = tid & 15;
        sinvs[tid] = 1.f / (sred[wqr * 2][rr] + sred[wqr * 2 + 1][rr]);
    }
    __syncthreads();
    float invx = sinvs[wq * 16 + g];
    float invy = sinvs[wq * 16 + g + 8];

    // ================= PASS 2: attn write + PV (fp16, 16-key steps) =================
    float* attnp = d_out + (size_t)BS * Dd
                 + ((size_t)((b * Hh + h) * Ss) + q0 + wq * 16) * Ss;

    float4 oacc[8];
    #pragma unroll
    for (int j = 0; j < 8; j++) oacc[j] = make_float4(0.f, 0.f, 0.f, 0.f);

    stage_kh(Kg, 0, sK0);
    stage_vth(VTg, 0, sV0);
    CP_COMMIT();

    for (int kt = 0; kt < 16; kt++) {
        if (kt < 15) {
            __syncthreads();
            stage_kh(Kg, kt + 1, (kt & 1) ? sK0 : sK1);
            stage_vth(VTg, kt + 1, (kt & 1) ? sV0 : sV1);
            CP_COMMIT();
            cp_wait<1>();
        } else {
            cp_wait<0>();
        }
        __syncthreads();

        const __half2* cK = (kt & 1) ? sK1 : sK0;
        const __half2* cV = (kt & 1) ? sV1 : sV0;

        #pragma unroll
        for (int j2 = 0; j2 < 4; j2++) {
            // two adjacent 8-key QK tiles
            float4 accA = make_float4(0.f, 0.f, 0.f, 0.f);
            float4 accB = make_float4(0.f, 0.f, 0.f, 0.f);
            const __half2* kpA = &cK[(wk2 * 64 + (2 * j2) * 8 + g) * KH2S + t];
            const __half2* kpB = kpA + 8 * KH2S;
            #pragma unroll
            for (int ks = 0; ks < 4; ks++) {
                mma_f16(accA, qa[ks], h2u(kpA[8 * ks]), h2u(kpA[8 * ks + 4]));
                mma_f16(accB, qa[ks], h2u(kpB[8 * ks]), h2u(kpB[8 * ks + 4]));
            }
            float4 bfA = b2[kt * 4096 + (2 * j2) * 32];
            float4 bfB = b2[kt * 4096 + (2 * j2 + 1) * 32];
            float4 pA, pB;
            pA.x = __expf(fmaf(accA.x, scale, bfA.x)) * invx;
            pA.y = __expf(fmaf(accA.y, scale, bfA.y)) * invx;
            pA.z = __expf(fmaf(accA.z, scale, bfA.z)) * invy;
            pA.w = __expf(fmaf(accA.w, scale, bfA.w)) * invy;
            pB.x = __expf(fmaf(accB.x, scale, bfB.x)) * invx;
            pB.y = __expf(fmaf(accB.y, scale, bfB.y)) * invx;
            pB.z = __expf(fmaf(accB.z, scale, bfB.z)) * invy;
            pB.w = __expf(fmaf(accB.w, scale, bfB.w)) * invy;

            int gcA = kt * 128 + wk2 * 64 + (2 * j2) * 8 + 2 * t;
            *(float2*)&attnp[(size_t)g * Ss + gcA] = make_float2(pA.x, pA.y);
            *(float2*)&attnp[(size_t)(g + 8) * Ss + gcA] = make_float2(pA.z, pA.w);
            *(float2*)&attnp[(size_t)g * Ss + gcA + 8] = make_float2(pB.x, pB.y);
            *(float2*)&attnp[(size_t)(g + 8) * Ss + gcA + 8] = make_float2(pB.z, pB.w);

            // PV A-frag (m16n8k16, keys j2*16 + {2t,2t+1,2t+8,2t+9}); no shuffles
            uint32_t A[4];
            A[0] = h2u(__floats2half2_rn(pA.x, pA.y));
            A[1] = h2u(__floats2half2_rn(pA.z, pA.w));
            A[2] = h2u(__floats2half2_rn(pB.x, pB.y));
            A[3] = h2u(__floats2half2_rn(pB.z, pB.w));

            #pragma unroll
            for (int jj = 0; jj < 8; jj++) {
                const __half2* vp = &cV[(jj * 8 + g) * VTH2S + wk2 * 32 + 8 * j2 + t];
                mma_f16(oacc[jj], A, h2u(vp[0]), h2u(vp[4]));
            }
        }
    }

    // ---- combine wk2 halves via smem (alias staging buffers), write g_x ----
    __syncthreads();
    float* sacc = (float*)smemh;   // 8 wq * 8 jj * 128 floats = 8192 floats
    if (wk2 == 1) {
        float* dst = &sacc[(wq * 8) * 128 + lane * 4];
        #pragma unroll
        for (int jj = 0; jj < 8; jj++) *(float4*)&dst[jj * 128] = oacc[jj];
    }
    __syncthreads();
    if (wk2 == 0) {
        const float* srcp = &sacc[(wq * 8) * 128 + lane * 4];
        #pragma unroll
        for (int jj = 0; jj < 8; jj++) {
            float4 o2 = *(const float4*)&srcp[jj * 128];
            float4 o = oacc[jj];
            o.x += o2.x; o.y += o2.y; o.z += o2.z; o.w += o2.w;
            int row0 = b * Ss + q0 + wq * 16 + g;
            int col = h * DK + jj * 8 + 2 * t;
            float2 r0, r1;
            r0.x = rnd_tf32(o.x); r0.y = rnd_tf32(o.y);
            r1.x = rnd_tf32(o.z); r1.y = rnd_tf32(o.w);
            *(float2*)&g_x[(size_t)row0 * Dd + col] = r0;
            *(float2*)&g_x[(size_t)(row0 + 8) * Dd + col] = r1;
        }
    }
}

// ---------------- launch ----------------
extern "C" void kernel_launch(void* const* d_in, const int* in_sizes, int n_in,
                              void* d_out, int out_size) {
    const float* q    = (const float*)d_in[0];
    const float* k    = (const float*)d_in[1];
    const float* v    = (const float*)d_in[2];
    const int*   mask = (const int*)  d_in[3];
    const float* pos  = (const float*)d_in[4];
    const float* ln_g = (const float*)d_in[5];
    const float* ln_b = (const float*)d_in[6];
    const float* wq   = (const float*)d_in[7];
    const float* bq   = (const float*)d_in[8];
    const float* wk   = (const float*)d_in[9];
    const float* bk   = (const float*)d_in[10];
    const float* wv   = (const float*)d_in[11];
    const float* bv   = (const float*)d_in[12];
    const float* wo   = (const float*)d_in[13];
    const float* bo   = (const float*)d_in[14];
    const float* ls   = (const float*)d_in[15];
    float* out = (float*)d_out;

    cudaFuncSetAttribute(attn_kernel, cudaFuncAttributeMaxDynamicSharedMemorySize,
                         ATTN_SMEM_BYTES);

    bias2_kernel<<<1024, 1024>>>(pos, mask);
    ln_kernel<<<dim3(BS, 3), 256>>>(q, k, v, ln_g, ln_b);
    wt_kernel<<<dim3(16, 16, 4), 256>>>(wq, wk, wv, wo);
    proj_qkv_kernel<<<dim3(BS / 64, Dd / 64, 3), 256>>>(bq, bk, bv);
    attn_kernel<<<dim3(Ss / 128, Hh, Bb), 512, ATTN_SMEM_BYTES>>>(out);
    proj_out_kernel<<<dim3(BS / 64, Dd / 64), 256>>>(bo, ls, out);
}

// round 16
// speedup vs baseline: 1.6955x; 1.1023x over previous
#include <cuda_runtime.h>
#include <cuda_fp16.h>
#include <math.h>
#include <stdint.h>

#define Bb 4
#define Ss 2048
#define Dd 512
#define Hh 8
#define DK 64
#define BS (Bb*Ss)          // 8192 rows
#define LN_EPS 1e-5f
#define NEG_BIG (-1e30f)

// ---------------- scratch (static device globals; no allocation) ----------------
__device__ __half  g_xnh[3][(size_t)BS*Dd];              // normalized q,k,v (fp16)
__device__ __half2 g_qkh[2][(size_t)Bb*Hh*Ss*(DK/2)];    // Q,K fp16 head-major [s][d/2]
__device__ __half  g_vth[(size_t)Bb*Hh*DK*Ss];           // V fp16 transposed [d][key]
__device__ __half2 g_xh[(size_t)BS*Dd/2];                // attention output (fp16)
__device__ __half  g_wth[4][(size_t)Dd*Dd];              // W^T fp16: [n][k]
__device__ float   g_bias2[(size_t)Ss*Ss];               // bias in mma-fragment order

// ---------------- helpers ----------------
__device__ __forceinline__ void mma_f16(float4& d, const uint32_t a[4],
                                        uint32_t b0, uint32_t b1) {
    asm volatile(
        "mma.sync.aligned.m16n8k16.row.col.f32.f16.f16.f32 "
        "{%0,%1,%2,%3}, {%4,%5,%6,%7}, {%8,%9}, {%0,%1,%2,%3};\n"
        : "+f"(d.x), "+f"(d.y), "+f"(d.z), "+f"(d.w)
        : "r"(a[0]), "r"(a[1]), "r"(a[2]), "r"(a[3]), "r"(b0), "r"(b1));
}

__device__ __forceinline__ void cpa16(void* s, const void* g) {
    uint32_t sa = (uint32_t)__cvta_generic_to_shared(s);
    asm volatile("cp.async.ca.shared.global [%0], [%1], 16;\n" :: "r"(sa), "l"(g));
}
#define CP_COMMIT() asm volatile("cp.async.commit_group;\n")
template<int N> __device__ __forceinline__ void cp_wait() {
    asm volatile("cp.async.wait_group %0;\n" :: "n"(N));
}

__device__ __forceinline__ uint32_t h2u(__half2 h) { return *(uint32_t*)&h; }

// ---------------- Kernel 0: pack mask+pos into mma-fragment-ordered bias ----------------
__global__ void __launch_bounds__(1024) bias2_kernel(
    const float* __restrict__ pos, const int* __restrict__ mask) {
    int idx = blockIdx.x * 1024 + threadIdx.x;      // 0 .. 1,048,575
    int lane = idx & 31;
    int j    = (idx >> 5) & 7;
    int w    = (idx >> 8) & 15;
    int kt   = (idx >> 12) & 15;
    int qt   = idx >> 16;                            // 0..15
    int g = lane >> 2, t = lane & 3;
    int wq = w >> 1, wk2 = w & 1;
    int q = qt * 128 + wq * 16 + g;
    int c = kt * 128 + wk2 * 64 + j * 8 + 2 * t;
    const float* p0 = &pos[q * Ss + c];
    const float* p1 = &pos[(q + 8) * Ss + c];
    const int*   m0 = &mask[q * Ss + c];
    const int*   m1 = &mask[(q + 8) * Ss + c];
    float4 o;
    o.x = m0[0] ? p0[0] : NEG_BIG;
    o.y = m0[1] ? p0[1] : NEG_BIG;
    o.z = m1[0] ? p1[0] : NEG_BIG;
    o.w = m1[1] ? p1[1] : NEG_BIG;
    ((float4*)g_bias2)[idx] = o;
}

// ---------------- Kernel 1: LayerNorm (fp16 output) ----------------
__global__ void ln_kernel(const float* __restrict__ q, const float* __restrict__ k,
                          const float* __restrict__ v, const float* __restrict__ g,
                          const float* __restrict__ b) {
    int row = blockIdx.x;
    int which = blockIdx.y;
    const float* xs = which == 0 ? q : (which == 1 ? k : v);
    const float* x = xs + (size_t)row * Dd;
    __half* y = g_xnh[which] + (size_t)row * Dd;
    int t = threadIdx.x;

    float v0 = x[t], v1 = x[t + 256];
    float s = v0 + v1, s2 = v0 * v0 + v1 * v1;

    __shared__ float rs[8], rs2[8];
    #pragma unroll
    for (int o = 16; o; o >>= 1) {
        s  += __shfl_xor_sync(0xFFFFFFFFu, s,  o);
        s2 += __shfl_xor_sync(0xFFFFFFFFu, s2, o);
    }
    if ((t & 31) == 0) { rs[t >> 5] = s; rs2[t >> 5] = s2; }
    __syncthreads();
    __shared__ float smu, sinv;
    if (t == 0) {
        float S = 0.f, S2 = 0.f;
        #pragma unroll
        for (int i = 0; i < 8; i++) { S += rs[i]; S2 += rs2[i]; }
        float mu = S * (1.f / 512.f);
        float var = S2 * (1.f / 512.f) - mu * mu;
        smu = mu; sinv = rsqrtf(var + LN_EPS);
    }
    __syncthreads();
    float mu = smu, inv = sinv;
    y[t]       = __float2half_rn((v0 - mu) * inv * g[t]       + b[t]);
    y[t + 256] = __float2half_rn((v1 - mu) * inv * g[t + 256] + b[t + 256]);
}

// ---------------- Kernel 1b: weight transpose + fp16 ----------------
__global__ void wt_kernel(const float* __restrict__ wq, const float* __restrict__ wk,
                          const float* __restrict__ wv, const float* __restrict__ wo) {
    __shared__ float tile[32][33];
    int z = blockIdx.z;
    const float* W = z == 0 ? wq : (z == 1 ? wk : (z == 2 ? wv : wo));
    int k0 = blockIdx.x * 32, n0 = blockIdx.y * 32;
    int c = threadIdx.x & 31, r0 = threadIdx.x >> 5;
    #pragma unroll
    for (int i = 0; i < 4; i++) {
        int r = r0 + i * 8;
        tile[r][c] = W[(size_t)(k0 + r) * Dd + n0 + c];
    }
    __syncthreads();
    #pragma unroll
    for (int i = 0; i < 4; i++) {
        int r = r0 + i * 8;
        g_wth[z][(size_t)(n0 + r) * Dd + k0 + c] = __float2half_rn(tile[c][r]);
    }
}

// ---------------- fp16 GEMM tile core (BM=64, BN=64, BK=32, m16n8k16, 2-stage) ----------------
#define GH 20                 // half2 per smem row (16 + 4 pad)
#define GSTG_H (64 * GH)      // 1280 half2 per stage per matrix

__device__ __forceinline__ void gemm_load_stage_h(
    const __half* __restrict__ A, const __half* __restrict__ Bt,
    int m0, int n0, int k0, __half2* sA, __half2* sB) {
    int tid = threadIdx.x;
    int m = tid >> 2, c = tid & 3;                 // 64 rows x 4 chunks (16B = 8 half)
    cpa16(&sA[m * GH + c * 4], &A[(size_t)(m0 + m) * Dd + k0 + c * 8]);
    cpa16(&sB[m * GH + c * 4], &Bt[(size_t)(n0 + m) * Dd + k0 + c * 8]);
}

__device__ __forceinline__ void gemm_tile_f16(
    const __half* __restrict__ A, const __half* __restrict__ Bt,
    int m0, int n0, float4 acc[2][2], __half2* sA, __half2* sB) {
    int tid = threadIdx.x;
    int lane = tid & 31, w = tid >> 5;
    int g = lane >> 2, t = lane & 3;
    int wm = w >> 2, wn = w & 3;
    #pragma unroll
    for (int i = 0; i < 2; i++)
        #pragma unroll
        for (int j = 0; j < 2; j++) acc[i][j] = make_float4(0.f, 0.f, 0.f, 0.f);

    gemm_load_stage_h(A, Bt, m0, n0, 0, sA, sB);
    CP_COMMIT();

    for (int it = 0; it < 16; it++) {
        if (it < 15) {
            int s = (it + 1) & 1;
            gemm_load_stage_h(A, Bt, m0, n0, (it + 1) * 32, sA + s * GSTG_H, sB + s * GSTG_H);
            CP_COMMIT();
            cp_wait<1>();
        } else {
            cp_wait<0>();
        }
        __syncthreads();

        const __half2* cA = sA + (it & 1) * GSTG_H;
        const __half2* cB = sB + (it & 1) * GSTG_H;
        #pragma unroll
        for (int ks = 0; ks < 2; ks++) {
            int kk2 = ks * 8;
            uint32_t a[2][4];
            #pragma unroll
            for (int mi = 0; mi < 2; mi++) {
                const __half2* ap = &cA[(wm * 32 + mi * 16 + g) * GH + kk2 + t];
                a[mi][0] = h2u(ap[0]);
                a[mi][1] = h2u(ap[8 * GH]);
                a[mi][2] = h2u(ap[4]);
                a[mi][3] = h2u(ap[8 * GH + 4]);
            }
            #pragma unroll
            for (int nj = 0; nj < 2; nj++) {
                const __half2* bp = &cB[(wn * 16 + nj * 8 + g) * GH + kk2 + t];
                uint32_t b0 = h2u(bp[0]);
                uint32_t b1 = h2u(bp[4]);
                mma_f16(acc[0][nj], a[0], b0, b1);
                mma_f16(acc[1][nj], a[1], b0, b1);
            }
        }
        __syncthreads();
    }
}

// ---------------- Kernel 2: QKV projection (Q,K fp16 head-major; V fp16 transposed) ----------------
__global__ void __launch_bounds__(256) proj_qkv_kernel(
    const float* __restrict__ bq, const float* __restrict__ bk, const float* __restrict__ bv) {
    __shared__ __half2 sA[2 * GSTG_H];
    __shared__ __half2 sB[2 * GSTG_H];
    int z = blockIdx.z;
    const float* bias = z == 0 ? bq : (z == 1 ? bk : bv);
    int m0 = blockIdx.x * 64, n0 = blockIdx.y * 64;

    float4 acc[2][2];
    gemm_tile_f16(g_xnh[z], g_wth[z], m0, n0, acc, sA, sB);

    int lane = threadIdx.x & 31, w = threadIdx.x >> 5;
    int g = lane >> 2, t = lane & 3;
    int wm = w >> 2, wn = w & 3;
    #pragma unroll
    for (int mi = 0; mi < 2; mi++) {
        #pragma unroll
        for (int nj = 0; nj < 2; nj++) {
            int n = n0 + wn * 16 + nj * 8 + 2 * t;
            int hh = n >> 6, dd = n & 63;
            float b0 = bias[n], b1 = bias[n + 1];
            #pragma unroll
            for (int r = 0; r < 2; r++) {
                int m = m0 + wm * 32 + mi * 16 + g + r * 8;
                int bidx = m >> 11, srow = m & 2047;
                float vx, vy;
                if (r == 0) { vx = acc[mi][nj].x + b0; vy = acc[mi][nj].y + b1; }
                else        { vx = acc[mi][nj].z + b0; vy = acc[mi][nj].w + b1; }
                if (z == 2) {
                    __half* VT = g_vth + (size_t)(bidx * Hh + hh) * DK * Ss;
                    VT[(size_t)dd * Ss + srow]       = __float2half_rn(vx);
                    VT[(size_t)(dd + 1) * Ss + srow] = __float2half_rn(vy);
                } else {
                    __half2* out = g_qkh[z] + ((size_t)(bidx * Hh + hh) * Ss + srow) * (DK / 2);
                    out[dd >> 1] = __floats2half2_rn(vx, vy);
                }
            }
        }
    }
}

// ---------------- Kernel 4: output projection (fp16 mma + layer_scale) ----------------
__global__ void __launch_bounds__(256) proj_out_kernel(
    const float* __restrict__ bo, const float* __restrict__ ls, float* __restrict__ Cout) {
    __shared__ __half2 sA[2 * GSTG_H];
    __shared__ __half2 sB[2 * GSTG_H];
    int m0 = blockIdx.x * 64, n0 = blockIdx.y * 64;

    float4 acc[2][2];
    gemm_tile_f16((const __half*)g_xh, g_wth[3], m0, n0, acc, sA, sB);

    int lane = threadIdx.x & 31, w = threadIdx.x >> 5;
    int g = lane >> 2, t = lane & 3;
    int wm = w >> 2, wn = w & 3;
    #pragma unroll
    for (int mi = 0; mi < 2; mi++) {
        #pragma unroll
        for (int nj = 0; nj < 2; nj++) {
            int n = n0 + wn * 16 + nj * 8 + 2 * t;
            float b0 = bo[n], b1 = bo[n + 1];
            float l0 = ls[n], l1 = ls[n + 1];
            #pragma unroll
            for (int r = 0; r < 2; r++) {
                int m = m0 + wm * 32 + mi * 16 + g + r * 8;
                float2 val;
                if (r == 0) { val.x = (acc[mi][nj].x + b0) * l0; val.y = (acc[mi][nj].y + b1) * l1; }
                else        { val.x = (acc[mi][nj].z + b0) * l0; val.y = (acc[mi][nj].w + b1) * l1; }
                *(float2*)&Cout[(size_t)m * Dd + n] = val;
            }
        }
    }
}

// ---------------- Kernel 3: attention — TQ=128, two-pass, fp16 m16n8k16 ----------------
#define KH2S 36                         // half2 per K smem row (32 + 4 pad)
#define VTH2S 68                        // half2 per VT smem row (64 + 4 pad)
#define SKH_ELEMS (128 * KH2S)          // 4608 half2
#define SVTH_ELEMS (64 * VTH2S)         // 4352 half2
#define ATTN_SMEM_BYTES ((2 * SKH_ELEMS + 2 * SVTH_ELEMS) * 4)   // 71,680
#define FULLM 0xFFFFFFFFu

__device__ __forceinline__ void stage_kh(const __half2* __restrict__ Kg, int kt, __half2* dst) {
    int tid = threadIdx.x;
    #pragma unroll
    for (int i = 0; i < 2; i++) {
        int idx = tid + i * 512;            // 1024 chunks = 128 keys x 8
        int key = idx >> 3, c = idx & 7;
        cpa16(&dst[key * KH2S + c * 4], &Kg[(size_t)(kt * 128 + key) * (DK / 2) + c * 4]);
    }
}
__device__ __forceinline__ void stage_vth(const __half* __restrict__ VTg, int kt, __half2* dst) {
    int tid = threadIdx.x;
    #pragma unroll
    for (int i = 0; i < 2; i++) {
        int idx = tid + i * 512;            // 1024 chunks = 64 d-rows x 16
        int d = idx >> 4, c = idx & 15;
        cpa16(&dst[d * VTH2S + c * 4], &VTg[(size_t)d * Ss + kt * 128 + c * 8]);
    }
}

__global__ void __launch_bounds__(512, 1) attn_kernel(float* __restrict__ d_out) {
    extern __shared__ __half2 smemh[];
    __half2* sK0 = smemh;
    __half2* sK1 = smemh + SKH_ELEMS;
    __half2* sV0 = smemh + 2 * SKH_ELEMS;
    __half2* sV1 = sV0 + SVTH_ELEMS;
    __shared__ float sred[16][16];
    __shared__ float sinvs[128];

    int qb = blockIdx.x, h = blockIdx.y, b = blockIdx.z;
    const __half2* Qg = g_qkh[0] + (size_t)(b * Hh + h) * Ss * (DK / 2);
    const __half2* Kg = g_qkh[1] + (size_t)(b * Hh + h) * Ss * (DK / 2);
    const __half*  VTg = g_vth   + (size_t)(b * Hh + h) * DK * Ss;
    int q0 = qb * 128;

    int tid = threadIdx.x;
    int lane = tid & 31, w = tid >> 5;
    int g = lane >> 2, t = lane & 3;
    int wq = w >> 1, wk2 = w & 1;
    const float scale = 0.125f;

    // Q fragments for m16n8k16
    uint32_t qa[4][4];
    {
        const __half2* Qr0 = Qg + (size_t)(q0 + wq * 16 + g) * (DK / 2);
        const __half2* Qr1 = Qg + (size_t)(q0 + wq * 16 + g + 8) * (DK / 2);
        #pragma unroll
        for (int ks = 0; ks < 4; ks++) {
            qa[ks][0] = h2u(Qr0[8 * ks + t]);
            qa[ks][1] = h2u(Qr1[8 * ks + t]);
            qa[ks][2] = h2u(Qr0[8 * ks + t + 4]);
            qa[ks][3] = h2u(Qr1[8 * ks + t + 4]);
        }
    }

    const float4* b2 = (const float4*)g_bias2 + ((size_t)(qb * 16) * 16 + w) * 256 + lane;

    // ================= PASS 1: row sums =================
    float2 rsum = make_float2(0.f, 0.f);
    stage_kh(Kg, 0, sK0);
    CP_COMMIT();

    for (int kt = 0; kt < 16; kt++) {
        if (kt < 15) {
            __syncthreads();
            stage_kh(Kg, kt + 1, (kt & 1) ? sK0 : sK1);
            CP_COMMIT();
            cp_wait<1>();
        } else {
            cp_wait<0>();
        }
        __syncthreads();

        const __half2* cK = (kt & 1) ? sK1 : sK0;
        #pragma unroll
        for (int j = 0; j < 8; j++) {
            float4 acc = make_float4(0.f, 0.f, 0.f, 0.f);
            const __half2* kp = &cK[(wk2 * 64 + j * 8 + g) * KH2S + t];
            #pragma unroll
            for (int ks = 0; ks < 4; ks++) {
                mma_f16(acc, qa[ks], h2u(kp[8 * ks]), h2u(kp[8 * ks + 4]));
            }
            float4 bf = b2[kt * 4096 + j * 32];
            float e0 = __expf(fmaf(acc.x, scale, bf.x));
            float e1 = __expf(fmaf(acc.y, scale, bf.y));
            float e2 = __expf(fmaf(acc.z, scale, bf.z));
            float e3 = __expf(fmaf(acc.w, scale, bf.w));
            rsum.x += e0 + e1;
            rsum.y += e2 + e3;
        }
    }

    rsum.x += __shfl_xor_sync(FULLM, rsum.x, 1);
    rsum.x += __shfl_xor_sync(FULLM, rsum.x, 2);
    rsum.y += __shfl_xor_sync(FULLM, rsum.y, 1);
    rsum.y += __shfl_xor_sync(FULLM, rsum.y, 2);
    if (t == 0) {
        sred[w][g] = rsum.x;
        sred[w][g + 8] = rsum.y;
    }
    __syncthreads();
    if (tid < 128) {
        int wqr = tid >> 4, rr = tid & 15;
        sinvs[tid] = 1.f / (sred[wqr * 2][rr] + sred[wqr * 2 + 1][rr]);
    }
    __syncthreads();
    float invx = sinvs[wq * 16 + g];
    float invy = sinvs[wq * 16 + g + 8];

    // ================= PASS 2: attn write + PV =================
    float* attnp = d_out + (size_t)BS * Dd
                 + ((size_t)((b * Hh + h) * Ss) + q0 + wq * 16) * Ss;

    float4 oacc[8];
    #pragma unroll
    for (int j = 0; j < 8; j++) oacc[j] = make_float4(0.f, 0.f, 0.f, 0.f);

    stage_kh(Kg, 0, sK0);
    stage_vth(VTg, 0, sV0);
    CP_COMMIT();

    for (int kt = 0; kt < 16; kt++) {
        if (kt < 15) {
            __syncthreads();
            stage_kh(Kg, kt + 1, (kt & 1) ? sK0 : sK1);
            stage_vth(VTg, kt + 1, (kt & 1) ? sV0 : sV1);
            CP_COMMIT();
            cp_wait<1>();
        } else {
            cp_wait<0>();
        }
        __syncthreads();

        const __half2* cK = (kt & 1) ? sK1 : sK0;
        const __half2* cV = (kt & 1) ? sV1 : sV0;

        #pragma unroll
        for (int j2 = 0; j2 < 4; j2++) {
            float4 accA = make_float4(0.f, 0.f, 0.f, 0.f);
            float4 accB = make_float4(0.f, 0.f, 0.f, 0.f);
            const __half2* kpA = &cK[(wk2 * 64 + (2 * j2) * 8 + g) * KH2S + t];
            const __half2* kpB = kpA + 8 * KH2S;
            #pragma unroll
            for (int ks = 0; ks < 4; ks++) {
                mma_f16(accA, qa[ks], h2u(kpA[8 * ks]), h2u(kpA[8 * ks + 4]));
                mma_f16(accB, qa[ks], h2u(kpB[8 * ks]), h2u(kpB[8 * ks + 4]));
            }
            float4 bfA = b2[kt * 4096 + (2 * j2) * 32];
            float4 bfB = b2[kt * 4096 + (2 * j2 + 1) * 32];
            float4 pA, pB;
            pA.x = __expf(fmaf(accA.x, scale, bfA.x)) * invx;
            pA.y = __expf(fmaf(accA.y, scale, bfA.y)) * invx;
            pA.z = __expf(fmaf(accA.z, scale, bfA.z)) * invy;
            pA.w = __expf(fmaf(accA.w, scale, bfA.w)) * invy;
            pB.x = __expf(fmaf(accB.x, scale, bfB.x)) * invx;
            pB.y = __expf(fmaf(accB.y, scale, bfB.y)) * invx;
            pB.z = __expf(fmaf(accB.z, scale, bfB.z)) * invy;
            pB.w = __expf(fmaf(accB.w, scale, bfB.w)) * invy;

            int gcA = kt * 128 + wk2 * 64 + (2 * j2) * 8 + 2 * t;
            *(float2*)&attnp[(size_t)g * Ss + gcA] = make_float2(pA.x, pA.y);
            *(float2*)&attnp[(size_t)(g + 8) * Ss + gcA] = make_float2(pA.z, pA.w);
            *(float2*)&attnp[(size_t)g * Ss + gcA + 8] = make_float2(pB.x, pB.y);
            *(float2*)&attnp[(size_t)(g + 8) * Ss + gcA + 8] = make_float2(pB.z, pB.w);

            uint32_t A[4];
            A[0] = h2u(__floats2half2_rn(pA.x, pA.y));
            A[1] = h2u(__floats2half2_rn(pA.z, pA.w));
            A[2] = h2u(__floats2half2_rn(pB.x, pB.y));
            A[3] = h2u(__floats2half2_rn(pB.z, pB.w));

            #pragma unroll
            for (int jj = 0; jj < 8; jj++) {
                const __half2* vp = &cV[(jj * 8 + g) * VTH2S + wk2 * 32 + 8 * j2 + t];
                mma_f16(oacc[jj], A, h2u(vp[0]), h2u(vp[4]));
            }
        }
    }

    // ---- combine wk2 halves via smem (alias staging buffers), write g_xh (fp16) ----
    __syncthreads();
    float* sacc = (float*)smemh;
    if (wk2 == 1) {
        float* dst = &sacc[(wq * 8) * 128 + lane * 4];
        #pragma unroll
        for (int jj = 0; jj < 8; jj++) *(float4*)&dst[jj * 128] = oacc[jj];
    }
    __syncthreads();
    if (wk2 == 0) {
        const float* srcp = &sacc[(wq * 8) * 128 + lane * 4];
        #pragma unroll
        for (int jj = 0; jj < 8; jj++) {
            float4 o2 = *(const float4*)&srcp[jj * 128];
            float4 o = oacc[jj];
            o.x += o2.x; o.y += o2.y; o.z += o2.z; o.w += o2.w;
            int row0 = b * Ss + q0 + wq * 16 + g;
            int col = h * DK + jj * 8 + 2 * t;
            g_xh[((size_t)row0 * Dd + col) >> 1]       = __floats2half2_rn(o.x, o.y);
            g_xh[((size_t)(row0 + 8) * Dd + col) >> 1] = __floats2half2_rn(o.z, o.w);
        }
    }
}

// ---------------- launch ----------------
extern "C" void kernel_launch(void* const* d_in, const int* in_sizes, int n_in,
                              void* d_out, int out_size) {
    const float* q    = (const float*)d_in[0];
    const float* k    = (const float*)d_in[1];
    const float* v    = (const float*)d_in[2];
    const int*   mask = (const int*)  d_in[3];
    const float* pos  = (const float*)d_in[4];
    const float* ln_g = (const float*)d_in[5];
    const float* ln_b = (const float*)d_in[6];
    const float* wq   = (const float*)d_in[7];
    const float* bq   = (const float*)d_in[8];
    const float* wk   = (const float*)d_in[9];
    const float* bk   = (const float*)d_in[10];
    const float* wv   = (const float*)d_in[11];
    const float* bv   = (const float*)d_in[12];
    const float* wo   = (const float*)d_in[13];
    const float* bo   = (const float*)d_in[14];
    const float* ls   = (const float*)d_in[15];
    float* out = (float*)d_out;

    cudaFuncSetAttribute(attn_kernel, cudaFuncAttributeMaxDynamicSharedMemorySize,
                         ATTN_SMEM_BYTES);

    bias2_kernel<<<1024, 1024>>>(pos, mask);
    ln_kernel<<<dim3(BS, 3), 256>>>(q, k, v, ln_g, ln_b);
    wt_kernel<<<dim3(16, 16, 4), 256>>>(wq, wk, wv, wo);
    proj_qkv_kernel<<<dim3(BS / 64, Dd / 64, 3), 256>>>(bq, bk, bv);
    attn_kernel<<<dim3(Ss / 128, Hh, Bb), 512, ATTN_SMEM_BYTES>>>(out);
    proj_out_kernel<<<dim3(BS / 64, Dd / 64), 256>>>(bo, ls, out);
}

// round 17
// speedup vs baseline: 1.8132x; 1.0694x over previous
#include <cuda_runtime.h>
#include <cuda_fp16.h>
#include <math.h>
#include <stdint.h>

#define Bb 4
#define Ss 2048
#define Dd 512
#define Hh 8
#define DK 64
#define BS (Bb*Ss)          // 8192 rows
#define LN_EPS 1e-5f
#define NEG_BIG (-1e30f)

// ---------------- scratch (static device globals; no allocation) ----------------
__device__ __half  g_xnh[3][(size_t)BS*Dd];              // normalized q,k,v (fp16)
__device__ __half2 g_qkh[2][(size_t)Bb*Hh*Ss*(DK/2)];    // Q,K fp16 head-major [s][d/2]
__device__ __half  g_vth[(size_t)Bb*Hh*DK*Ss];           // V fp16 transposed [d][key]
__device__ __half2 g_xh[(size_t)BS*Dd/2];                // attention output (fp16)
__device__ __half  g_wth[4][(size_t)Dd*Dd];              // W^T fp16: [n][k]
__device__ float   g_bias2[(size_t)Ss*Ss];               // bias in mma-fragment order

// ---------------- helpers ----------------
__device__ __forceinline__ void mma_f16(float4& d, const uint32_t a[4],
                                        uint32_t b0, uint32_t b1) {
    asm volatile(
        "mma.sync.aligned.m16n8k16.row.col.f32.f16.f16.f32 "
        "{%0,%1,%2,%3}, {%4,%5,%6,%7}, {%8,%9}, {%0,%1,%2,%3};\n"
        : "+f"(d.x), "+f"(d.y), "+f"(d.z), "+f"(d.w)
        : "r"(a[0]), "r"(a[1]), "r"(a[2]), "r"(a[3]), "r"(b0), "r"(b1));
}

__device__ __forceinline__ void cpa16(void* s, const void* g) {
    uint32_t sa = (uint32_t)__cvta_generic_to_shared(s);
    asm volatile("cp.async.cg.shared.global [%0], [%1], 16;\n" :: "r"(sa), "l"(g));
}
#define CP_COMMIT() asm volatile("cp.async.commit_group;\n")
template<int N> __device__ __forceinline__ void cp_wait() {
    asm volatile("cp.async.wait_group %0;\n" :: "n"(N));
}

__device__ __forceinline__ uint32_t h2u(__half2 h) { return *(uint32_t*)&h; }

// ---------------- Kernel 0: pack mask+pos into mma-fragment-ordered bias ----------------
__global__ void __launch_bounds__(1024) bias2_kernel(
    const float* __restrict__ pos, const int* __restrict__ mask) {
    int idx = blockIdx.x * 1024 + threadIdx.x;      // 0 .. 1,048,575
    int lane = idx & 31;
    int j    = (idx >> 5) & 7;
    int w    = (idx >> 8) & 15;
    int kt   = (idx >> 12) & 15;
    int qt   = idx >> 16;                            // 0..15
    int g = lane >> 2, t = lane & 3;
    int wq = w >> 1, wk2 = w & 1;
    int q = qt * 128 + wq * 16 + g;
    int c = kt * 128 + wk2 * 64 + j * 8 + 2 * t;
    const float* p0 = &pos[q * Ss + c];
    const float* p1 = &pos[(q + 8) * Ss + c];
    const int*   m0 = &mask[q * Ss + c];
    const int*   m1 = &mask[(q + 8) * Ss + c];
    float4 o;
    o.x = m0[0] ? p0[0] : NEG_BIG;
    o.y = m0[1] ? p0[1] : NEG_BIG;
    o.z = m1[0] ? p1[0] : NEG_BIG;
    o.w = m1[1] ? p1[1] : NEG_BIG;
    ((float4*)g_bias2)[idx] = o;
}

// ---------------- Kernel 1: LayerNorm (fp16 output) ----------------
__global__ void ln_kernel(const float* __restrict__ q, const float* __restrict__ k,
                          const float* __restrict__ v, const float* __restrict__ g,
                          const float* __restrict__ b) {
    int row = blockIdx.x;
    int which = blockIdx.y;
    const float* xs = which == 0 ? q : (which == 1 ? k : v);
    const float* x = xs + (size_t)row * Dd;
    __half* y = g_xnh[which] + (size_t)row * Dd;
    int t = threadIdx.x;

    float v0 = x[t], v1 = x[t + 256];
    float s = v0 + v1, s2 = v0 * v0 + v1 * v1;

    __shared__ float rs[8], rs2[8];
    #pragma unroll
    for (int o = 16; o; o >>= 1) {
        s  += __shfl_xor_sync(0xFFFFFFFFu, s,  o);
        s2 += __shfl_xor_sync(0xFFFFFFFFu, s2, o);
    }
    if ((t & 31) == 0) { rs[t >> 5] = s; rs2[t >> 5] = s2; }
    __syncthreads();
    __shared__ float smu, sinv;
    if (t == 0) {
        float S = 0.f, S2 = 0.f;
        #pragma unroll
        for (int i = 0; i < 8; i++) { S += rs[i]; S2 += rs2[i]; }
        float mu = S * (1.f / 512.f);
        float var = S2 * (1.f / 512.f) - mu * mu;
        smu = mu; sinv = rsqrtf(var + LN_EPS);
    }
    __syncthreads();
    float mu = smu, inv = sinv;
    y[t]       = __float2half_rn((v0 - mu) * inv * g[t]       + b[t]);
    y[t + 256] = __float2half_rn((v1 - mu) * inv * g[t + 256] + b[t + 256]);
}

// ---------------- Kernel 1b: weight transpose + fp16 ----------------
__global__ void wt_kernel(const float* __restrict__ wq, const float* __restrict__ wk,
                          const float* __restrict__ wv, const float* __restrict__ wo) {
    __shared__ float tile[32][33];
    int z = blockIdx.z;
    const float* W = z == 0 ? wq : (z == 1 ? wk : (z == 2 ? wv : wo));
    int k0 = blockIdx.x * 32, n0 = blockIdx.y * 32;
    int c = threadIdx.x & 31, r0 = threadIdx.x >> 5;
    #pragma unroll
    for (int i = 0; i < 4; i++) {
        int r = r0 + i * 8;
        tile[r][c] = W[(size_t)(k0 + r) * Dd + n0 + c];
    }
    __syncthreads();
    #pragma unroll
    for (int i = 0; i < 4; i++) {
        int r = r0 + i * 8;
        g_wth[z][(size_t)(n0 + r) * Dd + k0 + c] = __float2half_rn(tile[c][r]);
    }
}

// ---------------- fp16 GEMM tile core (BM=128, BN=128, BK=32, 512 thr, 1-sync pipeline) ----------------
#define GH 20                 // half2 per smem row (16 + 4 pad)
#define GSTG_H (128 * GH)     // 2560 half2 per stage per matrix

__device__ __forceinline__ void gemm_load_stage_h(
    const __half* __restrict__ A, const __half* __restrict__ Bt,
    int m0, int n0, int k0, __half2* sA, __half2* sB) {
    int tid = threadIdx.x;
    int m = tid >> 2, c = tid & 3;                 // 128 rows x 4 chunks (16B = 8 half)
    cpa16(&sA[m * GH + c * 4], &A[(size_t)(m0 + m) * Dd + k0 + c * 8]);
    cpa16(&sB[m * GH + c * 4], &Bt[(size_t)(n0 + m) * Dd + k0 + c * 8]);
}

__device__ __forceinline__ void gemm_tile_f16(
    const __half* __restrict__ A, const __half* __restrict__ Bt,
    int m0, int n0, float4 acc[2][4], __half2* sA, __half2* sB) {
    int tid = threadIdx.x;
    int lane = tid & 31, w = tid >> 5;
    int g = lane >> 2, t = lane & 3;
    int wm = w >> 2, wn = w & 3;
    #pragma unroll
    for (int i = 0; i < 2; i++)
        #pragma unroll
        for (int j = 0; j < 4; j++) acc[i][j] = make_float4(0.f, 0.f, 0.f, 0.f);

    gemm_load_stage_h(A, Bt, m0, n0, 0, sA, sB);
    CP_COMMIT();

    for (int it = 0; it < 16; it++) {
        cp_wait<0>();
        __syncthreads();
        if (it < 15) {
            int s = (it + 1) & 1;
            gemm_load_stage_h(A, Bt, m0, n0, (it + 1) * 32, sA + s * GSTG_H, sB + s * GSTG_H);
            CP_COMMIT();
        }

        const __half2* cA = sA + (it & 1) * GSTG_H;
        const __half2* cB = sB + (it & 1) * GSTG_H;
        #pragma unroll
        for (int ks = 0; ks < 2; ks++) {
            int kk2 = ks * 8;
            uint32_t a[2][4];
            #pragma unroll
            for (int mi = 0; mi < 2; mi++) {
                const __half2* ap = &cA[(wm * 32 + mi * 16 + g) * GH + kk2 + t];
                a[mi][0] = h2u(ap[0]);
                a[mi][1] = h2u(ap[8 * GH]);
                a[mi][2] = h2u(ap[4]);
                a[mi][3] = h2u(ap[8 * GH + 4]);
            }
            #pragma unroll
            for (int nj = 0; nj < 4; nj++) {
                const __half2* bp = &cB[(wn * 32 + nj * 8 + g) * GH + kk2 + t];
                uint32_t b0 = h2u(bp[0]);
                uint32_t b1 = h2u(bp[4]);
                mma_f16(acc[0][nj], a[0], b0, b1);
                mma_f16(acc[1][nj], a[1], b0, b1);
            }
        }
        __syncthreads();   // compute done before next iter's stage overwrites other buffer
    }
}

// ---------------- Kernel 2: QKV projection (Q,K fp16 head-major; V fp16 transposed) ----------------
__global__ void __launch_bounds__(512) proj_qkv_kernel(
    const float* __restrict__ bq, const float* __restrict__ bk, const float* __restrict__ bv) {
    __shared__ __half2 sA[2 * GSTG_H];
    __shared__ __half2 sB[2 * GSTG_H];
    int z = blockIdx.z;
    const float* bias = z == 0 ? bq : (z == 1 ? bk : bv);
    int m0 = blockIdx.x * 128, n0 = blockIdx.y * 128;

    float4 acc[2][4];
    gemm_tile_f16(g_xnh[z], g_wth[z], m0, n0, acc, sA, sB);

    int lane = threadIdx.x & 31, w = threadIdx.x >> 5;
    int g = lane >> 2, t = lane & 3;
    int wm = w >> 2, wn = w & 3;
    #pragma unroll
    for (int mi = 0; mi < 2; mi++) {
        #pragma unroll
        for (int nj = 0; nj < 4; nj++) {
            int n = n0 + wn * 32 + nj * 8 + 2 * t;
            int hh = n >> 6, dd = n & 63;
            float b0 = bias[n], b1 = bias[n + 1];
            #pragma unroll
            for (int r = 0; r < 2; r++) {
                int m = m0 + wm * 32 + mi * 16 + g + r * 8;
                int bidx = m >> 11, srow = m & 2047;
                float vx, vy;
                if (r == 0) { vx = acc[mi][nj].x + b0; vy = acc[mi][nj].y + b1; }
                else        { vx = acc[mi][nj].z + b0; vy = acc[mi][nj].w + b1; }
                if (z == 2) {
                    __half* VT = g_vth + (size_t)(bidx * Hh + hh) * DK * Ss;
                    VT[(size_t)dd * Ss + srow]       = __float2half_rn(vx);
                    VT[(size_t)(dd + 1) * Ss + srow] = __float2half_rn(vy);
                } else {
                    __half2* out = g_qkh[z] + ((size_t)(bidx * Hh + hh) * Ss + srow) * (DK / 2);
                    out[dd >> 1] = __floats2half2_rn(vx, vy);
                }
            }
        }
    }
}

// ---------------- Kernel 4: output projection (fp16 mma + layer_scale) ----------------
__global__ void __launch_bounds__(512) proj_out_kernel(
    const float* __restrict__ bo, const float* __restrict__ ls, float* __restrict__ Cout) {
    __shared__ __half2 sA[2 * GSTG_H];
    __shared__ __half2 sB[2 * GSTG_H];
    int m0 = blockIdx.x * 128, n0 = blockIdx.y * 128;

    float4 acc[2][4];
    gemm_tile_f16((const __half*)g_xh, g_wth[3], m0, n0, acc, sA, sB);

    int lane = threadIdx.x & 31, w = threadIdx.x >> 5;
    int g = lane >> 2, t = lane & 3;
    int wm = w >> 2, wn = w & 3;
    #pragma unroll
    for (int mi = 0; mi < 2; mi++) {
        #pragma unroll
        for (int nj = 0; nj < 4; nj++) {
            int n = n0 + wn * 32 + nj * 8 + 2 * t;
            float b0 = bo[n], b1 = bo[n + 1];
            float l0 = ls[n], l1 = ls[n + 1];
            #pragma unroll
            for (int r = 0; r < 2; r++) {
                int m = m0 + wm * 32 + mi * 16 + g + r * 8;
                float2 val;
                if (r == 0) { val.x = (acc[mi][nj].x + b0) * l0; val.y = (acc[mi][nj].y + b1) * l1; }
                else        { val.x = (acc[mi][nj].z + b0) * l0; val.y = (acc[mi][nj].w + b1) * l1; }
                *(float2*)&Cout[(size_t)m * Dd + n] = val;
            }
        }
    }
}

// ---------------- Kernel 3: attention — TQ=128, two-pass, fp16 m16n8k16, 1-sync loops ----------------
#define KH2S 36                         // half2 per K smem row (32 + 4 pad)
#define VTH2S 68                        // half2 per VT smem row (64 + 4 pad)
#define SKH_ELEMS (128 * KH2S)          // 4608 half2
#define SVTH_ELEMS (64 * VTH2S)         // 4352 half2
#define ATTN_SMEM_BYTES ((2 * SKH_ELEMS + 2 * SVTH_ELEMS) * 4)   // 71,680
#define FULLM 0xFFFFFFFFu

__device__ __forceinline__ void stage_kh(const __half2* __restrict__ Kg, int kt, __half2* dst) {
    int tid = threadIdx.x;
    #pragma unroll
    for (int i = 0; i < 2; i++) {
        int idx = tid + i * 512;            // 1024 chunks = 128 keys x 8
        int key = idx >> 3, c = idx & 7;
        cpa16(&dst[key * KH2S + c * 4], &Kg[(size_t)(kt * 128 + key) * (DK / 2) + c * 4]);
    }
}
__device__ __forceinline__ void stage_vth(const __half* __restrict__ VTg, int kt, __half2* dst) {
    int tid = threadIdx.x;
    #pragma unroll
    for (int i = 0; i < 2; i++) {
        int idx = tid + i * 512;            // 1024 chunks = 64 d-rows x 16
        int d = idx >> 4, c = idx & 15;
        cpa16(&dst[d * VTH2S + c * 4], &VTg[(size_t)d * Ss + kt * 128 + c * 8]);
    }
}

__global__ void __launch_bounds__(512, 1) attn_kernel(float* __restrict__ d_out) {
    extern __shared__ __half2 smemh[];
    __half2* sK0 = smemh;
    __half2* sK1 = smemh + SKH_ELEMS;
    __half2* sV0 = smemh + 2 * SKH_ELEMS;
    __half2* sV1 = sV0 + SVTH_ELEMS;
    __shared__ float sred[16][16];
    __shared__ float sinvs[128];

    int qb = blockIdx.x, h = blockIdx.y, b = blockIdx.z;
    const __half2* Qg = g_qkh[0] + (size_t)(b * Hh + h) * Ss * (DK / 2);
    const __half2* Kg = g_qkh[1] + (size_t)(b * Hh + h) * Ss * (DK / 2);
    const __half*  VTg = g_vth   + (size_t)(b * Hh + h) * DK * Ss;
    int q0 = qb * 128;

    int tid = threadIdx.x;
    int lane = tid & 31, w = tid >> 5;
    int g = lane >> 2, t = lane & 3;
    int wq = w >> 1, wk2 = w & 1;
    const float scale = 0.125f;

    // Q fragments for m16n8k16
    uint32_t qa[4][4];
    {
        const __half2* Qr0 = Qg + (size_t)(q0 + wq * 16 + g) * (DK / 2);
        const __half2* Qr1 = Qg + (size_t)(q0 + wq * 16 + g + 8) * (DK / 2);
        #pragma unroll
        for (int ks = 0; ks < 4; ks++) {
            qa[ks][0] = h2u(Qr0[8 * ks + t]);
            qa[ks][1] = h2u(Qr1[8 * ks + t]);
            qa[ks][2] = h2u(Qr0[8 * ks + t + 4]);
            qa[ks][3] = h2u(Qr1[8 * ks + t + 4]);
        }
    }

    const float4* b2 = (const float4*)g_bias2 + ((size_t)(qb * 16) * 16 + w) * 256 + lane;

    // ================= PASS 1: row sums (1 sync/iter) =================
    float2 rsum = make_float2(0.f, 0.f);
    stage_kh(Kg, 0, sK0);
    CP_COMMIT();

    for (int kt = 0; kt < 16; kt++) {
        cp_wait<0>();
        __syncthreads();
        if (kt < 15) {
            stage_kh(Kg, kt + 1, (kt & 1) ? sK0 : sK1);
            CP_COMMIT();
        }

        const __half2* cK = (kt & 1) ? sK1 : sK0;
        #pragma unroll
        for (int j = 0; j < 8; j++) {
            float4 acc = make_float4(0.f, 0.f, 0.f, 0.f);
            const __half2* kp = &cK[(wk2 * 64 + j * 8 + g) * KH2S + t];
            #pragma unroll
            for (int ks = 0; ks < 4; ks++) {
                mma_f16(acc, qa[ks], h2u(kp[8 * ks]), h2u(kp[8 * ks + 4]));
            }
            float4 bf = b2[kt * 4096 + j * 32];
            float e0 = __expf(fmaf(acc.x, scale, bf.x));
            float e1 = __expf(fmaf(acc.y, scale, bf.y));
            float e2 = __expf(fmaf(acc.z, scale, bf.z));
            float e3 = __expf(fmaf(acc.w, scale, bf.w));
            rsum.x += e0 + e1;
            rsum.y += e2 + e3;
        }
        __syncthreads();
    }

    rsum.x += __shfl_xor_sync(FULLM, rsum.x, 1);
    rsum.x += __shfl_xor_sync(FULLM, rsum.x, 2);
    rsum.y += __shfl_xor_sync(FULLM, rsum.y, 1);
    rsum.y += __shfl_xor_sync(FULLM, rsum.y, 2);
    if (t == 0) {
        sred[w][g] = rsum.x;
        sred[w][g + 8] = rsum.y;
    }
    __syncthreads();
    if (tid < 128) {
        int wqr = tid >> 4, rr = tid & 15;
        sinvs[tid] = 1.f / (sred[wqr * 2][rr] + sred[wqr * 2 + 1][rr]);
    }
    __syncthreads();
    float invx = sinvs[wq * 16 + g];
    float invy = sinvs[wq * 16 + g + 8];

    // ================= PASS 2: attn write + PV (1 sync/iter) =================
    float* attnp = d_out + (size_t)BS * Dd
                 + ((size_t)((b * Hh + h) * Ss) + q0 + wq * 16) * Ss;

    float4 oacc[8];
    #pragma unroll
    for (int j = 0; j < 8; j++) oacc[j] = make_float4(0.f, 0.f, 0.f, 0.f);

    stage_kh(Kg, 0, sK0);
    stage_vth(VTg, 0, sV0);
    CP_COMMIT();

    for (int kt = 0; kt < 16; kt++) {
        cp_wait<0>();
        __syncthreads();
        if (kt < 15) {
            stage_kh(Kg, kt + 1, (kt & 1) ? sK0 : sK1);
            stage_vth(VTg, kt + 1, (kt & 1) ? sV0 : sV1);
            CP_COMMIT();
        }

        const __half2* cK = (kt & 1) ? sK1 : sK0;
        const __half2* cV = (kt & 1) ? sV1 : sV0;

        #pragma unroll
        for (int j2 = 0; j2 < 4; j2++) {
            float4 accA = make_float4(0.f, 0.f, 0.f, 0.f);
            float4 accB = make_float4(0.f, 0.f, 0.f, 0.f);
            const __half2* kpA = &cK[(wk2 * 64 + (2 * j2) * 8 + g) * KH2S + t];
            const __half2* kpB = kpA + 8 * KH2S;
            #pragma unroll
            for (int ks = 0; ks < 4; ks++) {
                mma_f16(accA, qa[ks], h2u(kpA[8 * ks]), h2u(kpA[8 * ks + 4]));
                mma_f16(accB, qa[ks], h2u(kpB[8 * ks]), h2u(kpB[8 * ks + 4]));
            }
            float4 bfA = b2[kt * 4096 + (2 * j2) * 32];
            float4 bfB = b2[kt * 4096 + (2 * j2 + 1) * 32];
            float4 pA, pB;
            pA.x = __expf(fmaf(accA.x, scale, bfA.x)) * invx;
            pA.y = __expf(fmaf(accA.y, scale, bfA.y)) * invx;
            pA.z = __expf(fmaf(accA.z, scale, bfA.z)) * invy;
            pA.w = __expf(fmaf(accA.w, scale, bfA.w)) * invy;
            pB.x = __expf(fmaf(accB.x, scale, bfB.x)) * invx;
            pB.y = __expf(fmaf(accB.y, scale, bfB.y)) * invx;
            pB.z = __expf(fmaf(accB.z, scale, bfB.z)) * invy;
            pB.w = __expf(fmaf(accB.w, scale, bfB.w)) * invy;

            int gcA = kt * 128 + wk2 * 64 + (2 * j2) * 8 + 2 * t;
            *(float2*)&attnp[(size_t)g * Ss + gcA] = make_float2(pA.x, pA.y);
            *(float2*)&attnp[(size_t)(g + 8) * Ss + gcA] = make_float2(pA.z, pA.w);
            *(float2*)&attnp[(size_t)g * Ss + gcA + 8] = make_float2(pB.x, pB.y);
            *(float2*)&attnp[(size_t)(g + 8) * Ss + gcA + 8] = make_float2(pB.z, pB.w);

            uint32_t A[4];
            A[0] = h2u(__floats2half2_rn(pA.x, pA.y));
            A[1] = h2u(__floats2half2_rn(pA.z, pA.w));
            A[2] = h2u(__floats2half2_rn(pB.x, pB.y));
            A[3] = h2u(__floats2half2_rn(pB.z, pB.w));

            #pragma unroll
            for (int jj = 0; jj < 8; jj++) {
                const __half2* vp = &cV[(jj * 8 + g) * VTH2S + wk2 * 32 + 8 * j2 + t];
                mma_f16(oacc[jj], A, h2u(vp[0]), h2u(vp[4]));
            }
        }
        __syncthreads();
    }

    // ---- combine wk2 halves via smem (alias staging buffers), write g_xh (fp16) ----
    __syncthreads();
    float* sacc = (float*)smemh;
    if (wk2 == 1) {
        float* dst = &sacc[(wq * 8) * 128 + lane * 4];
        #pragma unroll
        for (int jj = 0; jj < 8; jj++) *(float4*)&dst[jj * 128] = oacc[jj];
    }
    __syncthreads();
    if (wk2 == 0) {
        const float* srcp = &sacc[(wq * 8) * 128 + lane * 4];
        #pragma unroll
        for (int jj = 0; jj < 8; jj++) {
            float4 o2 = *(const float4*)&srcp[jj * 128];
            float4 o = oacc[jj];
            o.x += o2.x; o.y += o2.y; o.z += o2.z; o.w += o2.w;
            int row0 = b * Ss + q0 + wq * 16 + g;
            int col = h * DK + jj * 8 + 2 * t;
            g_xh[((size_t)row0 * Dd + col) >> 1]       = __floats2half2_rn(o.x, o.y);
            g_xh[((size_t)(row0 + 8) * Dd + col) >> 1] = __floats2half2_rn(o.z, o.w);
        }
    }
}

// ---------------- launch ----------------
extern "C" void kernel_launch(void* const* d_in, const int* in_sizes, int n_in,
                              void* d_out, int out_size) {
    const float* q    = (const float*)d_in[0];
    const float* k    = (const float*)d_in[1];
    const float* v    = (const float*)d_in[2];
    const int*   mask = (const int*)  d_in[3];
    const float* pos  = (const float*)d_in[4];
    const float* ln_g = (const float*)d_in[5];
    const float* ln_b = (const float*)d_in[6];
    const float* wq   = (const float*)d_in[7];
    const float* bq   = (const float*)d_in[8];
    const float* wk   = (const float*)d_in[9];
    const float* bk   = (const float*)d_in[10];
    const float* wv   = (const float*)d_in[11];
    const float* bv   = (const float*)d_in[12];
    const float* wo   = (const float*)d_in[13];
    const float* bo   = (const float*)d_in[14];
    const float* ls   = (const float*)d_in[15];
    float* out = (float*)d_out;

    cudaFuncSetAttribute(attn_kernel, cudaFuncAttributeMaxDynamicSharedMemorySize,
                         ATTN_SMEM_BYTES);

    bias2_kernel<<<1024, 1024>>>(pos, mask);
    ln_kernel<<<dim3(BS, 3), 256>>>(q, k, v, ln_g, ln_b);
    wt_kernel<<<dim3(16, 16, 4), 256>>>(wq, wk, wv, wo);
    proj_qkv_kernel<<<dim3(BS / 128, Dd / 128, 3), 512>>>(bq, bk, bv);
    attn_kernel<<<dim3(Ss / 128, Hh, Bb), 512, ATTN_SMEM_BYTES>>>(out);
    proj_out_kernel<<<dim3(BS / 128, Dd / 128), 512>>>(bo, ls, out);
}